// round 4
// baseline (speedup 1.0000x reference)
#include <cuda_runtime.h>
#include <cuda_bf16.h>

#define NN 100000
#define EE 1000000
#define HH 64
#define GG 512
#define BN_EPS 1e-5f

// ---------------- device scratch (no allocations allowed) ----------------
__device__ float g_h  [NN * HH];   // layer input (post-BN of previous layer)
__device__ float g_hl [NN * HH];   // post-GEMM (lin output)
__device__ float g_out[NN * HH];   // aggregated -> relu(y) in place
__device__ float g_dinv[NN];
__device__ int   g_deg [NN];
__device__ float g_sum  [3 * HH];
__device__ float g_sumsq[3 * HH];
__device__ float g_mean [HH];
__device__ float g_rstd [HH];

// ---------------- init: deg=1 (self loop), zero stats, zero pooled out ----
__global__ void k_init(float* __restrict__ dout)
{
    int i = blockIdx.x * blockDim.x + threadIdx.x;
    if (i < NN)            g_deg[i] = 1;
    if (i < GG * 3 * HH)   dout[i]  = 0.0f;
    if (i < 3 * HH) { g_sum[i] = 0.0f; g_sumsq[i] = 0.0f; }
}

// ---------------- degree over dst ----------------
__global__ void k_deg(const int* __restrict__ dst)
{
    int e = blockIdx.x * blockDim.x + threadIdx.x;
    if (e < EE) atomicAdd(&g_deg[dst[e]], 1);
}

__global__ void k_dinv()
{
    int i = blockIdx.x * blockDim.x + threadIdx.x;
    if (i < NN) g_dinv[i] = rsqrtf((float)g_deg[i]);
}

// ---------------- GEMM: HL = X @ W^T ; OUT = HL * dinv^2 (self-loop msg) ---
__global__ __launch_bounds__(128) void k_gemm(const float* __restrict__ X,
                                              const float* __restrict__ W)
{
    __shared__ float sWt[HH * HH];   // transposed: sWt[k*64 + o] = W[o*64 + k]
    int t = threadIdx.x;
    for (int i = t; i < HH * HH; i += 128) {
        int o = i >> 6, k = i & 63;
        sWt[k * HH + o] = W[i];
    }
    __syncthreads();

    int node = blockIdx.x * 128 + t;
    if (node >= NN) return;

    const float4* xr = (const float4*)(X + (long)node * HH);
    float acc[HH];
#pragma unroll
    for (int o = 0; o < HH; o++) acc[o] = 0.0f;

#pragma unroll 4
    for (int k4 = 0; k4 < 16; k4++) {
        float4 xv = xr[k4];
#pragma unroll
        for (int kk = 0; kk < 4; kk++) {
            float xs = (kk == 0) ? xv.x : (kk == 1) ? xv.y : (kk == 2) ? xv.z : xv.w;
            const float4* wr = (const float4*)(sWt + (k4 * 4 + kk) * HH);
#pragma unroll
            for (int o4 = 0; o4 < 16; o4++) {
                float4 w = wr[o4];
                acc[o4 * 4 + 0] = fmaf(xs, w.x, acc[o4 * 4 + 0]);
                acc[o4 * 4 + 1] = fmaf(xs, w.y, acc[o4 * 4 + 1]);
                acc[o4 * 4 + 2] = fmaf(xs, w.z, acc[o4 * 4 + 2]);
                acc[o4 * 4 + 3] = fmaf(xs, w.w, acc[o4 * 4 + 3]);
            }
        }
    }

    float d  = g_dinv[node];
    float d2 = d * d;
    float4* hlr  = (float4*)(g_hl  + (long)node * HH);
    float4* outr = (float4*)(g_out + (long)node * HH);
#pragma unroll
    for (int o4 = 0; o4 < 16; o4++) {
        float4 v = make_float4(acc[o4*4+0], acc[o4*4+1], acc[o4*4+2], acc[o4*4+3]);
        hlr[o4]  = v;
        outr[o4] = make_float4(v.x * d2, v.y * d2, v.z * d2, v.w * d2);
    }
}

// ---------------- edge scatter: OUT[dst] += norm * HL[src] ----------------
// 16 threads per edge, each handles one float4 chunk, vector reduction.
__global__ void k_edge(const int* __restrict__ src, const int* __restrict__ dst)
{
    int tid = blockIdx.x * blockDim.x + threadIdx.x;
    int e = tid >> 4;
    if (e >= EE) return;
    int q = tid & 15;

    int s = src[e];
    int d = dst[e];
    float nrm = g_dinv[s] * g_dinv[d];

    float4 v = *(const float4*)(g_hl + (long)s * HH + q * 4);
    float* p = g_out + (long)d * HH + q * 4;
    asm volatile("red.global.add.v4.f32 [%0], {%1, %2, %3, %4};"
                 :: "l"(p), "f"(v.x * nrm), "f"(v.y * nrm),
                    "f"(v.z * nrm), "f"(v.w * nrm)
                 : "memory");
}

// ---------------- relu(y + b) in place + per-channel sum/sumsq ------------
__global__ void k_stats(const float* __restrict__ b, int layer)
{
    int c  = threadIdx.x;   // 64 channels
    int ty = threadIdx.y;   // 4 row slices
    float bias = b[c];
    float s = 0.0f, s2 = 0.0f;

    for (int i = blockIdx.x * 4 + ty; i < NN; i += gridDim.x * 4) {
        float v = g_out[(long)i * HH + c] + bias;
        v = fmaxf(v, 0.0f);
        g_out[(long)i * HH + c] = v;
        s += v;
        s2 = fmaf(v, v, s2);
    }

    __shared__ float ss[4][HH], ss2[4][HH];
    ss[ty][c]  = s;
    ss2[ty][c] = s2;
    __syncthreads();
    if (ty == 0) {
        float t  = ss[0][c]  + ss[1][c]  + ss[2][c]  + ss[3][c];
        float t2 = ss2[0][c] + ss2[1][c] + ss2[2][c] + ss2[3][c];
        atomicAdd(&g_sum  [layer * HH + c], t);
        atomicAdd(&g_sumsq[layer * HH + c], t2);
    }
}

// ---------------- BN params ----------------
__global__ void k_bn(int layer)
{
    int c = threadIdx.x;
    float m = g_sum[layer * HH + c] * (1.0f / NN);
    float v = g_sumsq[layer * HH + c] * (1.0f / NN) - m * m;
    g_mean[c] = m;
    g_rstd[c] = rsqrtf(v + BN_EPS);
}

// ---------------- normalize + write h + segment pool (batch is sorted) ----
__global__ void k_norm_pool(const float* __restrict__ g, const float* __restrict__ beta,
                            const int* __restrict__ batch,
                            float* __restrict__ pool,    // d_out + layer*64, stride 192
                            float* __restrict__ hfinal)  // d_out + G*192 or null
{
    int c  = threadIdx.x;  // 64
    int ty = threadIdx.y;  // 4
    int base = blockIdx.x * 256;

    float m = g_mean[c], r = g_rstd[c];
    float gg = g[c], bb = beta[c];
    float scale = gg * r;

    float acc = 0.0f;
    int curg = -1;
    for (int j = ty; j < 256; j += 4) {
        int i = base + j;
        if (i >= NN) break;
        float v = (g_out[(long)i * HH + c] - m) * scale + bb;
        g_h[(long)i * HH + c] = v;
        if (hfinal) hfinal[(long)i * HH + c] = v;
        int gi = batch[i];
        if (gi != curg) {
            if (curg >= 0) atomicAdd(&pool[(long)curg * 192 + c], acc);
            curg = gi;
            acc = 0.0f;
        }
        acc += v;
    }
    if (curg >= 0) atomicAdd(&pool[(long)curg * 192 + c], acc);
}

// ---------------- host launcher ----------------
extern "C" void kernel_launch(void* const* d_in, const int* in_sizes, int n_in,
                              void* d_out, int out_size)
{
    const float* x     = (const float*)d_in[0];
    const int*   eidx  = (const int*)  d_in[1];
    const int*   batch = (const int*)  d_in[2];
    const int*   src   = eidx;        // edge_index[0]
    const int*   dst   = eidx + EE;   // edge_index[1]

    const float* W[3]    = { (const float*)d_in[3],  (const float*)d_in[7],  (const float*)d_in[11] };
    const float* b[3]    = { (const float*)d_in[4],  (const float*)d_in[8],  (const float*)d_in[12] };
    const float* gam[3]  = { (const float*)d_in[5],  (const float*)d_in[9],  (const float*)d_in[13] };
    const float* bet[3]  = { (const float*)d_in[6],  (const float*)d_in[10], (const float*)d_in[14] };

    float* out = (float*)d_out;

    float* d_h;
    cudaGetSymbolAddress((void**)&d_h, g_h);

    // setup
    k_init<<<(NN + 255) / 256, 256>>>(out);
    k_deg <<<(EE + 255) / 256, 256>>>(dst);
    k_dinv<<<(NN + 255) / 256, 256>>>();

    dim3 t64x4(64, 4);
    int statsGrid = 512;
    int npGrid = (NN + 255) / 256;

    const float* layer_in = x;
    for (int l = 0; l < 3; l++) {
        k_gemm<<<(NN + 127) / 128, 128>>>(layer_in, W[l]);
        k_edge<<<(EE * 16 + 255) / 256, 256>>>(src, dst);
        k_stats<<<statsGrid, t64x4>>>(b[l], l);
        k_bn<<<1, 64>>>(l);
        float* hfinal = (l == 2) ? (out + (long)GG * 192) : nullptr;
        k_norm_pool<<<npGrid, t64x4>>>(gam[l], bet[l], batch, out + l * 64, hfinal);
        layer_in = d_h;
    }
}

// round 5
// speedup vs baseline: 1.1368x; 1.1368x over previous
#include <cuda_runtime.h>
#include <cuda_bf16.h>

#define NN 100000
#define EE 1000000
#define HH 64
#define GG 512
#define BN_EPS 1e-5f

typedef unsigned long long ull;

// ---------------- device scratch (no allocations allowed) ----------------
__device__ __align__(16) float g_hl [NN * HH];   // lin output, pre-scaled by dinv[node]
__device__ __align__(16) float g_out[NN * HH];   // aggregate -> relu in place
__device__ float g_dinv[NN];
__device__ int   g_deg [NN];
__device__ int   g_cnt [GG];
__device__ float g_sum  [3 * HH];
__device__ float g_sumsq[3 * HH];
__device__ __align__(16) float g_scale [HH];   // BN scale of previous layer (1.0 for layer 0)
__device__ __align__(16) float g_dconst[HH];   // BN shift of previous layer
__device__ __align__(16) float g_cvec  [HH];   // dconst @ W_next^T  (0 for layer 0)

// ---------------- f32x2 helpers ----------------
__device__ __forceinline__ ull fma2(ull a, ull b, ull c) {
    ull d;
    asm("fma.rn.f32x2 %0, %1, %2, %3;" : "=l"(d) : "l"(a), "l"(b), "l"(c));
    return d;
}
__device__ __forceinline__ ull dup2(float x) {
    ull d;
    unsigned r = __float_as_uint(x);
    asm("mov.b64 %0, {%1, %1};" : "=l"(d) : "r"(r));
    return d;
}
__device__ __forceinline__ float2 unp2(ull a) {
    unsigned lo, hi;
    asm("mov.b64 {%0, %1}, %2;" : "=r"(lo), "=r"(hi) : "l"(a));
    return make_float2(__uint_as_float(lo), __uint_as_float(hi));
}

// ---------------- init ----------------
__global__ void k_init(float* __restrict__ dout)
{
    int i = blockIdx.x * blockDim.x + threadIdx.x;
    if (i < NN)            g_deg[i] = 1;          // self loop
    if (i < GG * 3 * HH)   dout[i]  = 0.0f;       // pooled region
    if (i < 3 * HH) { g_sum[i] = 0.0f; g_sumsq[i] = 0.0f; }
    if (i < HH)     { g_scale[i] = 1.0f; g_dconst[i] = 0.0f; g_cvec[i] = 0.0f; }
    if (i < GG)       g_cnt[i] = 0;
}

// ---------------- degree over dst ----------------
__global__ void k_deg(const int* __restrict__ dst)
{
    int e = blockIdx.x * blockDim.x + threadIdx.x;
    if (e < EE) atomicAdd(&g_deg[dst[e]], 1);
}

__global__ void k_dinv()
{
    int i = blockIdx.x * blockDim.x + threadIdx.x;
    if (i < NN) g_dinv[i] = rsqrtf((float)g_deg[i]);
}

// ---------------- per-graph node counts (batch is sorted) ----------------
__global__ void k_cnt(const int* __restrict__ batch)
{
    int t = blockIdx.x * blockDim.x + threadIdx.x;
    int start = t * 16;
    if (start >= NN) return;
    int end = min(start + 16, NN);
    int curg = batch[start], acc = 0;
    for (int i = start; i < end; i++) {
        int gi = batch[i];
        if (gi != curg) { atomicAdd(&g_cnt[curg], acc); curg = gi; acc = 0; }
        acc++;
    }
    atomicAdd(&g_cnt[curg], acc);
}

// ---------------- fused GEMM: HL = (scale*X + dconst) @ W^T  -------------
// = X @ (W*scale)^T + cvec.  Writes g_hl = HL * dinv (src pre-scale) and
// g_out = HL * dinv^2 (self-loop message init).
// 128 threads / block, 128 nodes / block. Thread (oh = tid&1, pn = tid>>1)
// computes 32 outputs (o-half oh) for nodes base+pn and base+64+pn,
// accumulating f32x2 pairs over o with packed fma.rn.f32x2.
__global__ __launch_bounds__(128) void k_gemm(const float* __restrict__ X,
                                              const float* __restrict__ W)
{
    __shared__ __align__(16) float  sW[HH * HH];   // sW[k*64+o] = W[o][k]*scale[k]
    __shared__ float4 sX[128 * 17];                // padded rows (17 float4 = 68 floats)
    int tid  = threadIdx.x;
    int base = blockIdx.x * 128;

    for (int i = tid; i < HH * HH; i += 128) {
        int o = i >> 6, k = i & 63;
        sW[k * HH + o] = W[i] * g_scale[k];
    }
    for (int i = tid; i < 128 * 16; i += 128) {
        int r = i >> 4, c4 = i & 15;
        int node = base + r;
        float4 v = make_float4(0.f, 0.f, 0.f, 0.f);
        if (node < NN) v = ((const float4*)X)[(size_t)node * 16 + c4];
        sX[r * 17 + c4] = v;
    }
    __syncthreads();

    int oh = tid & 1;
    int pn = tid >> 1;
    int n0 = base + pn, n1 = base + 64 + pn;

    ull a0[16], a1[16];
    const ulonglong2* cv = (const ulonglong2*)(g_cvec + oh * 32);
#pragma unroll
    for (int j = 0; j < 8; j++) {
        ulonglong2 c = cv[j];
        a0[2*j] = c.x; a0[2*j+1] = c.y;
        a1[2*j] = c.x; a1[2*j+1] = c.y;
    }

#pragma unroll 4
    for (int k4 = 0; k4 < 16; k4++) {
        float4 xv0 = sX[pn * 17 + k4];
        float4 xv1 = sX[(pn + 64) * 17 + k4];
#pragma unroll
        for (int kk = 0; kk < 4; kk++) {
            float xs0 = (kk == 0) ? xv0.x : (kk == 1) ? xv0.y : (kk == 2) ? xv0.z : xv0.w;
            float xs1 = (kk == 0) ? xv1.x : (kk == 1) ? xv1.y : (kk == 2) ? xv1.z : xv1.w;
            ull xx0 = dup2(xs0);
            ull xx1 = dup2(xs1);
            const ulonglong2* wr = (const ulonglong2*)(sW + (k4 * 4 + kk) * HH + oh * 32);
#pragma unroll
            for (int j = 0; j < 8; j++) {
                ulonglong2 w = wr[j];
                a0[2*j]   = fma2(xx0, w.x, a0[2*j]);
                a0[2*j+1] = fma2(xx0, w.y, a0[2*j+1]);
                a1[2*j]   = fma2(xx1, w.x, a1[2*j]);
                a1[2*j+1] = fma2(xx1, w.y, a1[2*j+1]);
            }
        }
    }

    if (n0 < NN) {
        float d = g_dinv[n0];
        float4* hl = (float4*)(g_hl  + (size_t)n0 * HH + oh * 32);
        float4* ot = (float4*)(g_out + (size_t)n0 * HH + oh * 32);
#pragma unroll
        for (int j = 0; j < 8; j++) {
            float2 lo = unp2(a0[2*j]), hi = unp2(a0[2*j+1]);
            float4 s = make_float4(lo.x * d, lo.y * d, hi.x * d, hi.y * d);
            hl[j] = s;
            ot[j] = make_float4(s.x * d, s.y * d, s.z * d, s.w * d);
        }
    }
    if (n1 < NN) {
        float d = g_dinv[n1];
        float4* hl = (float4*)(g_hl  + (size_t)n1 * HH + oh * 32);
        float4* ot = (float4*)(g_out + (size_t)n1 * HH + oh * 32);
#pragma unroll
        for (int j = 0; j < 8; j++) {
            float2 lo = unp2(a1[2*j]), hi = unp2(a1[2*j+1]);
            float4 s = make_float4(lo.x * d, lo.y * d, hi.x * d, hi.y * d);
            hl[j] = s;
            ot[j] = make_float4(s.x * d, s.y * d, s.z * d, s.w * d);
        }
    }
}

// ---------------- edge scatter: OUT[dst] += dinv[dst] * HL_scaled[src] ----
__global__ void k_edge(const int* __restrict__ src, const int* __restrict__ dst)
{
    int tid = blockIdx.x * blockDim.x + threadIdx.x;
    int e = tid >> 4;
    if (e >= EE) return;
    int q = tid & 15;

    int s = src[e];
    int d = dst[e];
    float nd = g_dinv[d];

    float4 v = *(const float4*)(g_hl + (size_t)s * HH + q * 4);
    float* p = g_out + (size_t)d * HH + q * 4;
    asm volatile("red.global.add.v4.f32 [%0], {%1, %2, %3, %4};"
                 :: "l"(p), "f"(v.x * nd), "f"(v.y * nd),
                    "f"(v.z * nd), "f"(v.w * nd)
                 : "memory");
}

// ------- relu(y+b) in place + sum/sumsq + raw segment pool (batch sorted) --
__global__ void k_stats(const float* __restrict__ b, const int* __restrict__ batch,
                        float* __restrict__ pool, int layer)
{
    int c  = threadIdx.x;   // 64 channels
    int ty = threadIdx.y;   // 4 row slices
    int base = blockIdx.x * 128;
    float bias = b[c];
    float s = 0.f, s2 = 0.f, acc = 0.f;
    int curg = -1;

    for (int j = ty; j < 128; j += 4) {
        int i = base + j;
        if (i >= NN) break;
        float v = g_out[(size_t)i * HH + c] + bias;
        v = fmaxf(v, 0.0f);
        g_out[(size_t)i * HH + c] = v;
        s += v;
        s2 = fmaf(v, v, s2);
        int gi = batch[i];
        if (gi != curg) {
            if (curg >= 0) atomicAdd(&pool[(size_t)curg * 192 + c], acc);
            curg = gi; acc = 0.f;
        }
        acc += v;
    }
    if (curg >= 0) atomicAdd(&pool[(size_t)curg * 192 + c], acc);

    __shared__ float ss[4][HH], ss2[4][HH];
    ss[ty][c]  = s;
    ss2[ty][c] = s2;
    __syncthreads();
    if (ty == 0) {
        atomicAdd(&g_sum  [layer * HH + c], ss[0][c]  + ss[1][c]  + ss[2][c]  + ss[3][c]);
        atomicAdd(&g_sumsq[layer * HH + c], ss2[0][c] + ss2[1][c] + ss2[2][c] + ss2[3][c]);
    }
}

// ---------------- BN params + fused constant vector for next GEMM --------
__global__ void k_bn(const float* __restrict__ g, const float* __restrict__ beta,
                     const float* __restrict__ Wnext, int layer)
{
    int c = threadIdx.x;   // 64
    float m   = g_sum  [layer * HH + c] * (1.0f / NN);
    float var = g_sumsq[layer * HH + c] * (1.0f / NN) - m * m;
    float r  = rsqrtf(var + BN_EPS);
    float sc = g[c] * r;
    float dc = beta[c] - m * sc;
    g_scale[c]  = sc;
    g_dconst[c] = dc;

    __shared__ float sdc[HH];
    sdc[c] = dc;
    __syncthreads();
    if (Wnext) {
        float acc = 0.f;
#pragma unroll 8
        for (int k = 0; k < HH; k++) acc = fmaf(sdc[k], Wnext[c * HH + k], acc);
        g_cvec[c] = acc;
    }
}

// ---------------- pooled fixup: pool = scale*raw + cnt*dconst -------------
__global__ void k_poolfin(float* __restrict__ pool)
{
    int idx = blockIdx.x * blockDim.x + threadIdx.x;
    if (idx >= GG * HH) return;
    int gph = idx >> 6, c = idx & 63;
    float raw = pool[(size_t)gph * 192 + c];
    pool[(size_t)gph * 192 + c] = g_scale[c] * raw + (float)g_cnt[gph] * g_dconst[c];
}

// ---------------- final h output: BN(layer2) applied to raw relu ----------
__global__ void k_hfinal(float* __restrict__ outh)
{
    int idx = blockIdx.x * blockDim.x + threadIdx.x;
    if (idx >= NN * 16) return;
    float4 v = ((const float4*)g_out)[idx];
    int c = (idx & 15) * 4;
    v.x = v.x * g_scale[c]     + g_dconst[c];
    v.y = v.y * g_scale[c + 1] + g_dconst[c + 1];
    v.z = v.z * g_scale[c + 2] + g_dconst[c + 2];
    v.w = v.w * g_scale[c + 3] + g_dconst[c + 3];
    ((float4*)outh)[idx] = v;
}

// ---------------- host launcher ----------------
extern "C" void kernel_launch(void* const* d_in, const int* in_sizes, int n_in,
                              void* d_out, int out_size)
{
    const float* x     = (const float*)d_in[0];
    const int*   eidx  = (const int*)  d_in[1];
    const int*   batch = (const int*)  d_in[2];
    const int*   src   = eidx;
    const int*   dst   = eidx + EE;

    const float* W[3]   = { (const float*)d_in[3],  (const float*)d_in[7],  (const float*)d_in[11] };
    const float* b[3]   = { (const float*)d_in[4],  (const float*)d_in[8],  (const float*)d_in[12] };
    const float* gam[3] = { (const float*)d_in[5],  (const float*)d_in[9],  (const float*)d_in[13] };
    const float* bet[3] = { (const float*)d_in[6],  (const float*)d_in[10], (const float*)d_in[14] };

    float* out = (float*)d_out;

    float* d_relu;
    cudaGetSymbolAddress((void**)&d_relu, g_out);

    k_init<<<(NN + 255) / 256, 256>>>(out);
    k_deg <<<(EE + 255) / 256, 256>>>(dst);
    k_cnt <<<(NN / 16 + 255) / 256, 256>>>(batch);
    k_dinv<<<(NN + 255) / 256, 256>>>();

    dim3 t64x4(64, 4);
    const float* layer_in = x;
    for (int l = 0; l < 3; l++) {
        k_gemm<<<(NN + 127) / 128, 128>>>(layer_in, W[l]);
        k_edge<<<(EE * 16 + 255) / 256, 256>>>(src, dst);
        k_stats<<<(NN + 127) / 128, t64x4>>>(b[l], batch, out + l * 64, l);
        k_bn<<<1, 64>>>(gam[l], bet[l], (l < 2) ? W[l + 1] : nullptr, l);
        k_poolfin<<<(GG * HH + 255) / 256, 256>>>(out + l * 64);
        layer_in = d_relu;   // next GEMM reads raw relu; BN folded via g_scale/g_cvec
    }
    k_hfinal<<<(NN * 16 + 255) / 256, 256>>>(out + (size_t)GG * 192);
}

// round 7
// speedup vs baseline: 1.4565x; 1.2813x over previous
#include <cuda_runtime.h>
#include <cuda_bf16.h>

#define NN 100000
#define EE 1000000
#define HH 64
#define GG 512
#define BN_EPS 1e-5f

#define SCAN_B 1024
#define NBLK ((NN + SCAN_B - 1) / SCAN_B)   // 98

typedef unsigned long long ull;

// ---------------- device scratch (no allocations allowed) ----------------
__device__ __align__(16) float g_hl [NN * HH];   // lin output, pre-scaled by dinv[node]
__device__ __align__(16) float g_out[NN * HH];   // relu(agg+bias), layer output (pre-BN; BN folded fwd)
__device__ float g_dinv[NN];
__device__ int   g_edeg[NN];        // edge-only in-degree
__device__ int   g_off [NN + 1];    // CSR offsets
__device__ int   g_cur [NN];        // bucket cursors
__device__ int   g_esrc[EE];        // src index bucketed by dst
__device__ int   g_part[NBLK];      // scan partials
__device__ int   g_cnt [GG];
__device__ float g_sum  [3 * HH];
__device__ float g_sumsq[3 * HH];
__device__ __align__(16) float g_scale [HH];   // BN scale of previous layer (1.0 for layer 0)
__device__ __align__(16) float g_dconst[HH];   // BN shift of previous layer
__device__ __align__(16) float g_cvec  [HH];   // dconst @ W_next^T  (0 for layer 0)

// ---------------- f32x2 helpers ----------------
__device__ __forceinline__ ull fma2(ull a, ull b, ull c) {
    ull d;
    asm("fma.rn.f32x2 %0, %1, %2, %3;" : "=l"(d) : "l"(a), "l"(b), "l"(c));
    return d;
}
__device__ __forceinline__ ull dup2(float x) {
    ull d;
    unsigned r = __float_as_uint(x);
    asm("mov.b64 %0, {%1, %1};" : "=l"(d) : "r"(r));
    return d;
}
__device__ __forceinline__ float2 unp2(ull a) {
    unsigned lo, hi;
    asm("mov.b64 {%0, %1}, %2;" : "=r"(lo), "=r"(hi) : "l"(a));
    return make_float2(__uint_as_float(lo), __uint_as_float(hi));
}

// ---------------- init ----------------
__global__ void k_init(float* __restrict__ dout)
{
    int i = blockIdx.x * blockDim.x + threadIdx.x;
    if (i < NN)            g_edeg[i] = 0;
    if (i < GG * 3 * HH)   dout[i]  = 0.0f;       // pooled region
    if (i < 3 * HH) { g_sum[i] = 0.0f; g_sumsq[i] = 0.0f; }
    if (i < HH)     { g_scale[i] = 1.0f; g_dconst[i] = 0.0f; g_cvec[i] = 0.0f; }
    if (i < GG)       g_cnt[i] = 0;
}

// ---------------- edge-only in-degree over dst ----------------
__global__ void k_deg(const int* __restrict__ dst)
{
    int e = blockIdx.x * blockDim.x + threadIdx.x;
    if (e < EE) atomicAdd(&g_edeg[dst[e]], 1);
}

// ---------------- exclusive scan of g_edeg -> g_off (3 passes) ----------
__global__ __launch_bounds__(SCAN_B) void k_scan1()
{
    __shared__ int sh[SCAN_B];
    int t = threadIdx.x;
    int i = blockIdx.x * SCAN_B + t;
    int v = (i < NN) ? g_edeg[i] : 0;
    sh[t] = v;
    __syncthreads();
    int val = v;
    for (int d = 1; d < SCAN_B; d <<= 1) {
        int add = (t >= d) ? sh[t - d] : 0;
        __syncthreads();
        val += add;
        sh[t] = val;
        __syncthreads();
    }
    if (i < NN) g_off[i] = val - v;                // local exclusive
    if (t == SCAN_B - 1) g_part[blockIdx.x] = val; // block total
}

__global__ void k_scan2()
{
    if (threadIdx.x == 0) {
        int run = 0;
        for (int i = 0; i < NBLK; i++) { int t = g_part[i]; g_part[i] = run; run += t; }
    }
}

__global__ void k_scan3()
{
    int i = blockIdx.x * blockDim.x + threadIdx.x;
    if (i < NN) {
        int o = g_off[i] + g_part[i / SCAN_B];
        g_off[i] = o;
        g_cur[i] = o;
    }
    if (i == 0) g_off[NN] = EE;
}

// ---------------- bucket edges by dst ----------------
__global__ void k_bucket(const int* __restrict__ src, const int* __restrict__ dst)
{
    int e = blockIdx.x * blockDim.x + threadIdx.x;
    if (e >= EE) return;
    int d = dst[e];
    int pos = atomicAdd(&g_cur[d], 1);
    g_esrc[pos] = src[e];
}

__global__ void k_dinv()
{
    int i = blockIdx.x * blockDim.x + threadIdx.x;
    if (i < NN) g_dinv[i] = rsqrtf((float)(g_edeg[i] + 1));   // +1 self loop
}

// ---------------- per-graph node counts (batch is sorted) ----------------
__global__ void k_cnt(const int* __restrict__ batch)
{
    int t = blockIdx.x * blockDim.x + threadIdx.x;
    int start = t * 16;
    if (start >= NN) return;
    int end = min(start + 16, NN);
    int curg = batch[start], acc = 0;
    for (int i = start; i < end; i++) {
        int gi = batch[i];
        if (gi != curg) { atomicAdd(&g_cnt[curg], acc); curg = gi; acc = 0; }
        acc++;
    }
    atomicAdd(&g_cnt[curg], acc);
}

// ---------------- fused GEMM: HL = (scale*X + dconst) @ W^T  -------------
// = X @ (W*scale)^T + cvec.  Writes g_hl = HL * dinv[node] only.
__global__ __launch_bounds__(128) void k_gemm(const float* __restrict__ X,
                                              const float* __restrict__ W)
{
    __shared__ __align__(16) float  sW[HH * HH];   // sW[k*64+o] = W[o][k]*scale[k]
    __shared__ float4 sX[128 * 17];
    int tid  = threadIdx.x;
    int base = blockIdx.x * 128;

    for (int i = tid; i < HH * HH; i += 128) {
        int o = i >> 6, k = i & 63;
        sW[k * HH + o] = W[i] * g_scale[k];
    }
    for (int i = tid; i < 128 * 16; i += 128) {
        int r = i >> 4, c4 = i & 15;
        int node = base + r;
        float4 v = make_float4(0.f, 0.f, 0.f, 0.f);
        if (node < NN) v = ((const float4*)X)[(size_t)node * 16 + c4];
        sX[r * 17 + c4] = v;
    }
    __syncthreads();

    int oh = tid & 1;
    int pn = tid >> 1;
    int n0 = base + pn, n1 = base + 64 + pn;

    ull a0[16], a1[16];
    const ulonglong2* cv = (const ulonglong2*)(g_cvec + oh * 32);
#pragma unroll
    for (int j = 0; j < 8; j++) {
        ulonglong2 c = cv[j];
        a0[2*j] = c.x; a0[2*j+1] = c.y;
        a1[2*j] = c.x; a1[2*j+1] = c.y;
    }

#pragma unroll 4
    for (int k4 = 0; k4 < 16; k4++) {
        float4 xv0 = sX[pn * 17 + k4];
        float4 xv1 = sX[(pn + 64) * 17 + k4];
#pragma unroll
        for (int kk = 0; kk < 4; kk++) {
            float xs0 = (kk == 0) ? xv0.x : (kk == 1) ? xv0.y : (kk == 2) ? xv0.z : xv0.w;
            float xs1 = (kk == 0) ? xv1.x : (kk == 1) ? xv1.y : (kk == 2) ? xv1.z : xv1.w;
            ull xx0 = dup2(xs0);
            ull xx1 = dup2(xs1);
            const ulonglong2* wr = (const ulonglong2*)(sW + (k4 * 4 + kk) * HH + oh * 32);
#pragma unroll
            for (int j = 0; j < 8; j++) {
                ulonglong2 w = wr[j];
                a0[2*j]   = fma2(xx0, w.x, a0[2*j]);
                a0[2*j+1] = fma2(xx0, w.y, a0[2*j+1]);
                a1[2*j]   = fma2(xx1, w.x, a1[2*j]);
                a1[2*j+1] = fma2(xx1, w.y, a1[2*j+1]);
            }
        }
    }

    if (n0 < NN) {
        float d = g_dinv[n0];
        float4* hl = (float4*)(g_hl + (size_t)n0 * HH + oh * 32);
#pragma unroll
        for (int j = 0; j < 8; j++) {
            float2 lo = unp2(a0[2*j]), hi = unp2(a0[2*j+1]);
            hl[j] = make_float4(lo.x * d, lo.y * d, hi.x * d, hi.y * d);
        }
    }
    if (n1 < NN) {
        float d = g_dinv[n1];
        float4* hl = (float4*)(g_hl + (size_t)n1 * HH + oh * 32);
#pragma unroll
        for (int j = 0; j < 8; j++) {
            float2 lo = unp2(a1[2*j]), hi = unp2(a1[2*j+1]);
            hl[j] = make_float4(lo.x * d, lo.y * d, hi.x * d, hi.y * d);
        }
    }
}

// ---- fused pull-aggregate + bias + relu + BN stats + raw segment pool ----
// 256 threads = 16 groups of 16; one node per group, one float4 (4 ch) per thread.
// acc_raw = hl_scaled[self] + sum_nbr hl_scaled[src];  y = relu(dinv*acc_raw + b)
__global__ __launch_bounds__(256) void k_agg(const float* __restrict__ b,
                                             const int* __restrict__ batch,
                                             float* __restrict__ pool, int layer)
{
    int tid = threadIdx.x;
    int grp = tid >> 4;
    int q   = tid & 15;
    int node = blockIdx.x * 16 + grp;      // grid is exactly NN/16

    unsigned mask = 0xFFFFu << (((tid & 31) >> 4) << 4);

    const float4* hl4 = (const float4*)g_hl;
    float4 acc = hl4[(size_t)node * 16 + q];   // self-loop term (norm = dinv^2, dinv factored)

    int beg = g_off[node], end = g_off[node + 1];
    for (int p = beg; p < end; p += 16) {
        int idx = (p + q < end) ? g_esrc[p + q] : 0;
        int cnt = min(16, end - p);
        for (int j = 0; j < cnt; j++) {
            int s = __shfl_sync(mask, idx, j, 16);
            float4 v = hl4[(size_t)s * 16 + q];
            acc.x += v.x; acc.y += v.y; acc.z += v.z; acc.w += v.w;
        }
    }

    float di = g_dinv[node];
    float4 bv = ((const float4*)b)[q];
    float4 y;
    y.x = fmaxf(fmaf(acc.x, di, bv.x), 0.f);
    y.y = fmaxf(fmaf(acc.y, di, bv.y), 0.f);
    y.z = fmaxf(fmaf(acc.z, di, bv.z), 0.f);
    y.w = fmaxf(fmaf(acc.w, di, bv.w), 0.f);
    ((float4*)g_out)[(size_t)node * 16 + q] = y;

    __shared__ float sY[16][HH + 4];
    __shared__ int   sB[16];
    sY[grp][q*4+0] = y.x;
    sY[grp][q*4+1] = y.y;
    sY[grp][q*4+2] = y.z;
    sY[grp][q*4+3] = y.w;
    if (q == 0) sB[grp] = batch[node];
    __syncthreads();

    if (tid < HH) {
        int c = tid;
        float s = 0.f, s2 = 0.f, pacc = 0.f;
        int curg = sB[0];
#pragma unroll
        for (int g2 = 0; g2 < 16; g2++) {
            float v = sY[g2][c];
            s += v;
            s2 = fmaf(v, v, s2);
            int gi = sB[g2];
            if (gi != curg) {
                atomicAdd(&pool[(size_t)curg * 192 + c], pacc);
                curg = gi; pacc = 0.f;
            }
            pacc += v;
        }
        atomicAdd(&pool[(size_t)curg * 192 + c], pacc);
        atomicAdd(&g_sum  [layer * HH + c], s);
        atomicAdd(&g_sumsq[layer * HH + c], s2);
    }
}

// ---------------- BN params + fused constant vector for next GEMM --------
__global__ void k_bn(const float* __restrict__ g, const float* __restrict__ beta,
                     const float* __restrict__ Wnext, int layer)
{
    int c = threadIdx.x;   // 64
    float m   = g_sum  [layer * HH + c] * (1.0f / NN);
    float var = g_sumsq[layer * HH + c] * (1.0f / NN) - m * m;
    float r  = rsqrtf(var + BN_EPS);
    float sc = g[c] * r;
    float dc = beta[c] - m * sc;
    g_scale[c]  = sc;
    g_dconst[c] = dc;

    __shared__ float sdc[HH];
    sdc[c] = dc;
    __syncthreads();
    if (Wnext) {
        float acc = 0.f;
#pragma unroll 8
        for (int k = 0; k < HH; k++) acc = fmaf(sdc[k], Wnext[c * HH + k], acc);
        g_cvec[c] = acc;
    }
}

// ---------------- pooled fixup: pool = scale*raw + cnt*dconst -------------
__global__ void k_poolfin(float* __restrict__ pool)
{
    int idx = blockIdx.x * blockDim.x + threadIdx.x;
    if (idx >= GG * HH) return;
    int gph = idx >> 6, c = idx & 63;
    float raw = pool[(size_t)gph * 192 + c];
    pool[(size_t)gph * 192 + c] = g_scale[c] * raw + (float)g_cnt[gph] * g_dconst[c];
}

// ---------------- final h output: BN(layer2) applied to raw relu ----------
__global__ void k_hfinal(float* __restrict__ outh)
{
    int idx = blockIdx.x * blockDim.x + threadIdx.x;
    if (idx >= NN * 16) return;
    float4 v = ((const float4*)g_out)[idx];
    int c = (idx & 15) * 4;
    v.x = v.x * g_scale[c]     + g_dconst[c];
    v.y = v.y * g_scale[c + 1] + g_dconst[c + 1];
    v.z = v.z * g_scale[c + 2] + g_dconst[c + 2];
    v.w = v.w * g_scale[c + 3] + g_dconst[c + 3];
    ((float4*)outh)[idx] = v;
}

// ---------------- host launcher ----------------
extern "C" void kernel_launch(void* const* d_in, const int* in_sizes, int n_in,
                              void* d_out, int out_size)
{
    const float* x     = (const float*)d_in[0];
    const int*   eidx  = (const int*)  d_in[1];
    const int*   batch = (const int*)  d_in[2];
    const int*   src   = eidx;
    const int*   dst   = eidx + EE;

    const float* W[3]   = { (const float*)d_in[3],  (const float*)d_in[7],  (const float*)d_in[11] };
    const float* b[3]   = { (const float*)d_in[4],  (const float*)d_in[8],  (const float*)d_in[12] };
    const float* gam[3] = { (const float*)d_in[5],  (const float*)d_in[9],  (const float*)d_in[13] };
    const float* bet[3] = { (const float*)d_in[6],  (const float*)d_in[10], (const float*)d_in[14] };

    float* out = (float*)d_out;

    float* d_relu;
    cudaGetSymbolAddress((void**)&d_relu, g_out);

    // setup: degrees, CSR, counts
    k_init  <<<(NN + 255) / 256, 256>>>(out);
    k_deg   <<<(EE + 255) / 256, 256>>>(dst);
    k_scan1 <<<NBLK, SCAN_B>>>();
    k_scan2 <<<1, 32>>>();
    k_scan3 <<<(NN + 255) / 256, 256>>>();
    k_bucket<<<(EE + 255) / 256, 256>>>(src, dst);
    k_cnt   <<<(NN / 16 + 255) / 256, 256>>>(batch);
    k_dinv  <<<(NN + 255) / 256, 256>>>();

    const float* layer_in = x;
    for (int l = 0; l < 3; l++) {
        k_gemm<<<(NN + 127) / 128, 128>>>(layer_in, W[l]);
        k_agg <<<NN / 16, 256>>>(b[l], batch, out + l * 64, l);
        k_bn  <<<1, 64>>>(gam[l], bet[l], (l < 2) ? W[l + 1] : nullptr, l);
        k_poolfin<<<(GG * HH + 255) / 256, 256>>>(out + l * 64);
        layer_in = d_relu;
    }
    k_hfinal<<<(NN * 16 + 255) / 256, 256>>>(out + (size_t)GG * 192);
}

// round 8
// speedup vs baseline: 1.5132x; 1.0389x over previous
#include <cuda_runtime.h>
#include <cuda_bf16.h>

#define NN 100000
#define EE 1000000
#define HH 64
#define GG 512
#define BN_EPS 1e-5f

#define SCAN_B 1024
#define NBLK ((NN + SCAN_B - 1) / SCAN_B)   // 98

typedef unsigned long long ull;

// ---------------- device scratch (no allocations allowed) ----------------
__device__ __align__(16) float g_hl [NN * HH];   // lin output, pre-scaled by dinv[node]
__device__ __align__(16) float g_out[NN * HH];   // relu(agg+bias) raw layer output
__device__ float g_dinv[NN];
__device__ int   g_edeg[NN];        // edge-only in-degree
__device__ int   g_off [NN + 1];    // CSR offsets
__device__ int   g_cur [NN];        // bucket cursors
__device__ int   g_esrc[EE];        // src index bucketed by dst
__device__ int   g_part[NBLK];      // scan partials
__device__ int   g_cnt [GG];
__device__ float g_sum  [3 * HH];
__device__ float g_sumsq[3 * HH];
__device__ __align__(16) float g_scale [HH];   // BN scale of previous layer (1.0 for layer 0)
__device__ __align__(16) float g_dconst[HH];   // BN shift of previous layer
__device__ __align__(16) float g_cvec  [HH];   // dconst @ W_next^T  (0 for layer 0)

// ---------------- f32x2 helpers ----------------
__device__ __forceinline__ ull fma2(ull a, ull b, ull c) {
    ull d;
    asm("fma.rn.f32x2 %0, %1, %2, %3;" : "=l"(d) : "l"(a), "l"(b), "l"(c));
    return d;
}
__device__ __forceinline__ ull dup2(float x) {
    ull d;
    unsigned r = __float_as_uint(x);
    asm("mov.b64 %0, {%1, %1};" : "=l"(d) : "r"(r));
    return d;
}
__device__ __forceinline__ float2 unp2(ull a) {
    unsigned lo, hi;
    asm("mov.b64 {%0, %1}, %2;" : "=r"(lo), "=r"(hi) : "l"(a));
    return make_float2(__uint_as_float(lo), __uint_as_float(hi));
}

// ---------------- init ----------------
__global__ void k_init(float* __restrict__ dout)
{
    int i = blockIdx.x * blockDim.x + threadIdx.x;
    if (i < NN)            g_edeg[i] = 0;
    if (i < GG * 3 * HH)   dout[i]  = 0.0f;       // pooled region
    if (i < 3 * HH) { g_sum[i] = 0.0f; g_sumsq[i] = 0.0f; }
    if (i < HH)     { g_scale[i] = 1.0f; g_dconst[i] = 0.0f; g_cvec[i] = 0.0f; }
    if (i < GG)       g_cnt[i] = 0;
}

// ---------------- edge-only in-degree over dst ----------------
__global__ void k_deg(const int* __restrict__ dst)
{
    int e = blockIdx.x * blockDim.x + threadIdx.x;
    if (e < EE) atomicAdd(&g_edeg[dst[e]], 1);
}

// ---------------- exclusive scan of g_edeg -> g_off ----------------------
__global__ __launch_bounds__(SCAN_B) void k_scan1()
{
    __shared__ int sh[SCAN_B];
    int t = threadIdx.x;
    int i = blockIdx.x * SCAN_B + t;
    int v = (i < NN) ? g_edeg[i] : 0;
    sh[t] = v;
    __syncthreads();
    int val = v;
    for (int d = 1; d < SCAN_B; d <<= 1) {
        int add = (t >= d) ? sh[t - d] : 0;
        __syncthreads();
        val += add;
        sh[t] = val;
        __syncthreads();
    }
    if (i < NN) g_off[i] = val - v;                // local exclusive
    if (t == SCAN_B - 1) g_part[blockIdx.x] = val; // block total
}

// parallel exclusive scan of 98 block totals (one 128-thread block)
__global__ __launch_bounds__(128) void k_scan2()
{
    __shared__ int warpSum[4];
    int t = threadIdx.x;
    int lane = t & 31, w = t >> 5;
    int v = (t < NBLK) ? g_part[t] : 0;
    int inc = v;
#pragma unroll
    for (int d = 1; d < 32; d <<= 1) {
        int n = __shfl_up_sync(0xFFFFFFFFu, inc, d);
        if (lane >= d) inc += n;
    }
    if (lane == 31) warpSum[w] = inc;
    __syncthreads();
    int base = 0;
    for (int j = 0; j < w; j++) base += warpSum[j];
    if (t < NBLK) g_part[t] = base + inc - v;      // exclusive
}

// scan finalize + dinv + per-graph node counts (fused)
__global__ void k_scan3(const int* __restrict__ batch)
{
    int i = blockIdx.x * blockDim.x + threadIdx.x;
    if (i < NN) {
        int o = g_off[i] + g_part[i / SCAN_B];
        g_off[i] = o;
        g_cur[i] = o;
        g_dinv[i] = rsqrtf((float)(g_edeg[i] + 1));   // +1 self loop
    }
    if (i == 0) g_off[NN] = EE;

    // per-graph node counts: thread i handles nodes [i*16, i*16+16)
    int start = i * 16;
    if (start < NN) {
        int end = min(start + 16, NN);
        int curg = batch[start], acc = 0;
        for (int n = start; n < end; n++) {
            int gi = batch[n];
            if (gi != curg) { atomicAdd(&g_cnt[curg], acc); curg = gi; acc = 0; }
            acc++;
        }
        atomicAdd(&g_cnt[curg], acc);
    }
}

// ---------------- bucket edges by dst ----------------
__global__ void k_bucket(const int* __restrict__ src, const int* __restrict__ dst)
{
    int e = blockIdx.x * blockDim.x + threadIdx.x;
    if (e >= EE) return;
    int d = dst[e];
    int pos = atomicAdd(&g_cur[d], 1);
    g_esrc[pos] = src[e];
}

// ---------------- fused GEMM: HL = (scale*X + dconst) @ W^T  -------------
// = X @ (W*scale)^T + cvec.  Writes g_hl = HL * dinv[node].
__global__ __launch_bounds__(128) void k_gemm(const float* __restrict__ X,
                                              const float* __restrict__ W)
{
    __shared__ __align__(16) float  sW[HH * HH];   // sW[k*64+o] = W[o][k]*scale[k]
    __shared__ float4 sX[128 * 17];
    int tid  = threadIdx.x;
    int base = blockIdx.x * 128;

    for (int i = tid; i < HH * HH; i += 128) {
        int o = i >> 6, k = i & 63;
        sW[k * HH + o] = W[i] * g_scale[k];
    }
    for (int i = tid; i < 128 * 16; i += 128) {
        int r = i >> 4, c4 = i & 15;
        int node = base + r;
        float4 v = make_float4(0.f, 0.f, 0.f, 0.f);
        if (node < NN) v = ((const float4*)X)[(size_t)node * 16 + c4];
        sX[r * 17 + c4] = v;
    }
    __syncthreads();

    int oh = tid & 1;
    int pn = tid >> 1;
    int n0 = base + pn, n1 = base + 64 + pn;

    ull a0[16], a1[16];
    const ulonglong2* cv = (const ulonglong2*)(g_cvec + oh * 32);
#pragma unroll
    for (int j = 0; j < 8; j++) {
        ulonglong2 c = cv[j];
        a0[2*j] = c.x; a0[2*j+1] = c.y;
        a1[2*j] = c.x; a1[2*j+1] = c.y;
    }

#pragma unroll 4
    for (int k4 = 0; k4 < 16; k4++) {
        float4 xv0 = sX[pn * 17 + k4];
        float4 xv1 = sX[(pn + 64) * 17 + k4];
#pragma unroll
        for (int kk = 0; kk < 4; kk++) {
            float xs0 = (kk == 0) ? xv0.x : (kk == 1) ? xv0.y : (kk == 2) ? xv0.z : xv0.w;
            float xs1 = (kk == 0) ? xv1.x : (kk == 1) ? xv1.y : (kk == 2) ? xv1.z : xv1.w;
            ull xx0 = dup2(xs0);
            ull xx1 = dup2(xs1);
            const ulonglong2* wr = (const ulonglong2*)(sW + (k4 * 4 + kk) * HH + oh * 32);
#pragma unroll
            for (int j = 0; j < 8; j++) {
                ulonglong2 w = wr[j];
                a0[2*j]   = fma2(xx0, w.x, a0[2*j]);
                a0[2*j+1] = fma2(xx0, w.y, a0[2*j+1]);
                a1[2*j]   = fma2(xx1, w.x, a1[2*j]);
                a1[2*j+1] = fma2(xx1, w.y, a1[2*j+1]);
            }
        }
    }

    if (n0 < NN) {
        float d = g_dinv[n0];
        float4* hl = (float4*)(g_hl + (size_t)n0 * HH + oh * 32);
#pragma unroll
        for (int j = 0; j < 8; j++) {
            float2 lo = unp2(a0[2*j]), hi = unp2(a0[2*j+1]);
            hl[j] = make_float4(lo.x * d, lo.y * d, hi.x * d, hi.y * d);
        }
    }
    if (n1 < NN) {
        float d = g_dinv[n1];
        float4* hl = (float4*)(g_hl + (size_t)n1 * HH + oh * 32);
#pragma unroll
        for (int j = 0; j < 8; j++) {
            float2 lo = unp2(a1[2*j]), hi = unp2(a1[2*j+1]);
            hl[j] = make_float4(lo.x * d, lo.y * d, hi.x * d, hi.y * d);
        }
    }
}

// ---- fused pull-aggregate + bias + relu + BN stats + raw segment pool ----
// 256 threads = 16 groups of 16; one node per group, one float4 (4 ch) per thread.
// Neighbor loop chunked by 4: unconditional loads (pad idx 0), predicated adds -> MLP=4.
__global__ __launch_bounds__(256) void k_agg(const float* __restrict__ b,
                                             const int* __restrict__ batch,
                                             float* __restrict__ pool, int layer)
{
    int tid = threadIdx.x;
    int grp = tid >> 4;
    int q   = tid & 15;
    int node = blockIdx.x * 16 + grp;      // grid is exactly NN/16

    unsigned mask = 0xFFFFu << (((tid & 31) >> 4) << 4);

    const float4* hl4 = (const float4*)g_hl;
    float4 acc = hl4[(size_t)node * 16 + q];   // self-loop term

    int beg = g_off[node], end = g_off[node + 1];
    for (int p = beg; p < end; p += 16) {
        int idx = (p + q < end) ? g_esrc[p + q] : 0;   // pad with node 0 (safe)
        int cnt = min(16, end - p);
#pragma unroll 1
        for (int j = 0; j < cnt; j += 4) {
            int s0 = __shfl_sync(mask, idx, j + 0, 16);
            int s1 = __shfl_sync(mask, idx, j + 1, 16);
            int s2 = __shfl_sync(mask, idx, j + 2, 16);
            int s3 = __shfl_sync(mask, idx, j + 3, 16);
            float4 v0 = hl4[(size_t)s0 * 16 + q];
            float4 v1 = hl4[(size_t)s1 * 16 + q];
            float4 v2 = hl4[(size_t)s2 * 16 + q];
            float4 v3 = hl4[(size_t)s3 * 16 + q];
            { acc.x += v0.x; acc.y += v0.y; acc.z += v0.z; acc.w += v0.w; }
            if (j + 1 < cnt) { acc.x += v1.x; acc.y += v1.y; acc.z += v1.z; acc.w += v1.w; }
            if (j + 2 < cnt) { acc.x += v2.x; acc.y += v2.y; acc.z += v2.z; acc.w += v2.w; }
            if (j + 3 < cnt) { acc.x += v3.x; acc.y += v3.y; acc.z += v3.z; acc.w += v3.w; }
        }
    }

    float di = g_dinv[node];
    float4 bv = ((const float4*)b)[q];
    float4 y;
    y.x = fmaxf(fmaf(acc.x, di, bv.x), 0.f);
    y.y = fmaxf(fmaf(acc.y, di, bv.y), 0.f);
    y.z = fmaxf(fmaf(acc.z, di, bv.z), 0.f);
    y.w = fmaxf(fmaf(acc.w, di, bv.w), 0.f);
    ((float4*)g_out)[(size_t)node * 16 + q] = y;

    __shared__ float sY[16][HH + 4];
    __shared__ int   sB[16];
    sY[grp][q*4+0] = y.x;
    sY[grp][q*4+1] = y.y;
    sY[grp][q*4+2] = y.z;
    sY[grp][q*4+3] = y.w;
    if (q == 0) sB[grp] = batch[node];
    __syncthreads();

    if (tid < HH) {
        int c = tid;
        float s = 0.f, s2 = 0.f, pacc = 0.f;
        int curg = sB[0];
#pragma unroll
        for (int g2 = 0; g2 < 16; g2++) {
            float v = sY[g2][c];
            s += v;
            s2 = fmaf(v, v, s2);
            int gi = sB[g2];
            if (gi != curg) {
                atomicAdd(&pool[(size_t)curg * 192 + c], pacc);
                curg = gi; pacc = 0.f;
            }
            pacc += v;
        }
        atomicAdd(&pool[(size_t)curg * 192 + c], pacc);
        atomicAdd(&g_sum  [layer * HH + c], s);
        atomicAdd(&g_sumsq[layer * HH + c], s2);
    }
}

// ---------------- BN params + fused constant vector for next GEMM --------
__global__ void k_bn(const float* __restrict__ g, const float* __restrict__ beta,
                     const float* __restrict__ Wnext, int layer)
{
    int c = threadIdx.x;   // 64
    float m   = g_sum  [layer * HH + c] * (1.0f / NN);
    float var = g_sumsq[layer * HH + c] * (1.0f / NN) - m * m;
    float r  = rsqrtf(var + BN_EPS);
    float sc = g[c] * r;
    float dc = beta[c] - m * sc;
    g_scale[c]  = sc;
    g_dconst[c] = dc;

    __shared__ float sdc[HH];
    sdc[c] = dc;
    __syncthreads();
    if (Wnext) {
        float acc = 0.f;
#pragma unroll 8
        for (int k = 0; k < HH; k++) acc = fmaf(sdc[k], Wnext[c * HH + k], acc);
        g_cvec[c] = acc;
    }
}

// ---------------- pooled fixup: pool = scale*raw + cnt*dconst -------------
__global__ void k_poolfin(float* __restrict__ pool)
{
    int idx = blockIdx.x * blockDim.x + threadIdx.x;
    if (idx >= GG * HH) return;
    int gph = idx >> 6, c = idx & 63;
    float raw = pool[(size_t)gph * 192 + c];
    pool[(size_t)gph * 192 + c] = g_scale[c] * raw + (float)g_cnt[gph] * g_dconst[c];
}

// ---------------- final h output: BN(layer2) applied to raw relu ----------
__global__ void k_hfinal(float* __restrict__ outh)
{
    int idx = blockIdx.x * blockDim.x + threadIdx.x;
    if (idx >= NN * 16) return;
    float4 v = ((const float4*)g_out)[idx];
    int c = (idx & 15) * 4;
    v.x = v.x * g_scale[c]     + g_dconst[c];
    v.y = v.y * g_scale[c + 1] + g_dconst[c + 1];
    v.z = v.z * g_scale[c + 2] + g_dconst[c + 2];
    v.w = v.w * g_scale[c + 3] + g_dconst[c + 3];
    ((float4*)outh)[idx] = v;
}

// ---------------- host launcher ----------------
extern "C" void kernel_launch(void* const* d_in, const int* in_sizes, int n_in,
                              void* d_out, int out_size)
{
    const float* x     = (const float*)d_in[0];
    const int*   eidx  = (const int*)  d_in[1];
    const int*   batch = (const int*)  d_in[2];
    const int*   src   = eidx;
    const int*   dst   = eidx + EE;

    const float* W[3]   = { (const float*)d_in[3],  (const float*)d_in[7],  (const float*)d_in[11] };
    const float* b[3]   = { (const float*)d_in[4],  (const float*)d_in[8],  (const float*)d_in[12] };
    const float* gam[3] = { (const float*)d_in[5],  (const float*)d_in[9],  (const float*)d_in[13] };
    const float* bet[3] = { (const float*)d_in[6],  (const float*)d_in[10], (const float*)d_in[14] };

    float* out = (float*)d_out;

    float* d_relu;
    cudaGetSymbolAddress((void**)&d_relu, g_out);

    // setup: degrees, CSR (scan fused with dinv + graph counts)
    k_init  <<<(NN + 255) / 256, 256>>>(out);
    k_deg   <<<(EE + 255) / 256, 256>>>(dst);
    k_scan1 <<<NBLK, SCAN_B>>>();
    k_scan2 <<<1, 128>>>();
    k_scan3 <<<(NN + 255) / 256, 256>>>(batch);
    k_bucket<<<(EE + 255) / 256, 256>>>(src, dst);

    const float* layer_in = x;
    for (int l = 0; l < 3; l++) {
        k_gemm<<<(NN + 127) / 128, 128>>>(layer_in, W[l]);
        k_agg <<<NN / 16, 256>>>(b[l], batch, out + l * 64, l);
        k_bn  <<<1, 64>>>(gam[l], bet[l], (l < 2) ? W[l + 1] : nullptr, l);
        k_poolfin<<<(GG * HH + 255) / 256, 256>>>(out + l * 64);
        layer_in = d_relu;
    }
    k_hfinal<<<(NN * 16 + 255) / 256, 256>>>(out + (size_t)GG * 192);
}

// round 10
// speedup vs baseline: 1.5245x; 1.0075x over previous
#include <cuda_runtime.h>
#include <cuda_bf16.h>

#define NN 100000
#define EE 1000000
#define HH 64
#define GG 512
#define BN_EPS 1e-5f

#define SCAN_B 1024
#define NBLK ((NN + SCAN_B - 1) / SCAN_B)   // 98

typedef unsigned long long ull;

// ---------------- device scratch (no allocations allowed) ----------------
__device__ __align__(16) float g_hl [NN * HH];   // lin output, pre-scaled by dinv[node]
__device__ __align__(16) float g_out[NN * HH];   // relu(agg+bias) raw layer output
__device__ float g_dinv[NN];
__device__ int   g_edeg[NN];        // edge-only in-degree
__device__ int   g_off [NN + 1];    // CSR offsets
__device__ int   g_cur [NN];        // bucket cursors
__device__ int   g_esrc[EE];        // src index bucketed by dst
__device__ int   g_part[NBLK];      // scan partials
__device__ int   g_cnt [GG];
__device__ float g_sum  [3 * HH];
__device__ float g_sumsq[3 * HH];
__device__ __align__(16) float g_scale [HH];   // BN scale of previous layer (1.0 for layer 0)
__device__ __align__(16) float g_dconst[HH];   // BN shift of previous layer
__device__ __align__(16) float g_cvec  [HH];   // dconst @ W_next^T  (0 for layer 0)

// ---------------- f32x2 helpers ----------------
__device__ __forceinline__ ull fma2(ull a, ull b, ull c) {
    ull d;
    asm("fma.rn.f32x2 %0, %1, %2, %3;" : "=l"(d) : "l"(a), "l"(b), "l"(c));
    return d;
}
__device__ __forceinline__ ull dup2(float x) {
    ull d;
    unsigned r = __float_as_uint(x);
    asm("mov.b64 %0, {%1, %1};" : "=l"(d) : "r"(r));
    return d;
}
__device__ __forceinline__ float2 unp2(ull a) {
    unsigned lo, hi;
    asm("mov.b64 {%0, %1}, %2;" : "=r"(lo), "=r"(hi) : "l"(a));
    return make_float2(__uint_as_float(lo), __uint_as_float(hi));
}

// ---------------- init ----------------
__global__ void k_init(float* __restrict__ dout)
{
    int i = blockIdx.x * blockDim.x + threadIdx.x;
    if (i < NN)            g_edeg[i] = 0;
    if (i < GG * 3 * HH)   dout[i]  = 0.0f;       // pooled region
    if (i < 3 * HH) { g_sum[i] = 0.0f; g_sumsq[i] = 0.0f; }
    if (i < HH)     { g_scale[i] = 1.0f; g_dconst[i] = 0.0f; g_cvec[i] = 0.0f; }
    if (i < GG)       g_cnt[i] = 0;
}

// ---------------- edge-only in-degree over dst ----------------
__global__ void k_deg(const int* __restrict__ dst)
{
    int e = blockIdx.x * blockDim.x + threadIdx.x;
    if (e < EE) atomicAdd(&g_edeg[dst[e]], 1);
}

// ---------------- exclusive scan of g_edeg -> g_off ----------------------
__global__ __launch_bounds__(SCAN_B) void k_scan1()
{
    __shared__ int sh[SCAN_B];
    int t = threadIdx.x;
    int i = blockIdx.x * SCAN_B + t;
    int v = (i < NN) ? g_edeg[i] : 0;
    sh[t] = v;
    __syncthreads();
    int val = v;
    for (int d = 1; d < SCAN_B; d <<= 1) {
        int add = (t >= d) ? sh[t - d] : 0;
        __syncthreads();
        val += add;
        sh[t] = val;
        __syncthreads();
    }
    if (i < NN) g_off[i] = val - v;                // local exclusive
    if (t == SCAN_B - 1) g_part[blockIdx.x] = val; // block total
}

// parallel exclusive scan of 98 block totals
__global__ __launch_bounds__(128) void k_scan2()
{
    __shared__ int warpSum[4];
    int t = threadIdx.x;
    int lane = t & 31, w = t >> 5;
    int v = (t < NBLK) ? g_part[t] : 0;
    int inc = v;
#pragma unroll
    for (int d = 1; d < 32; d <<= 1) {
        int n = __shfl_up_sync(0xFFFFFFFFu, inc, d);
        if (lane >= d) inc += n;
    }
    if (lane == 31) warpSum[w] = inc;
    __syncthreads();
    int base = 0;
    for (int j = 0; j < w; j++) base += warpSum[j];
    if (t < NBLK) g_part[t] = base + inc - v;      // exclusive
}

// scan finalize + dinv + per-graph node counts (fused)
__global__ void k_scan3(const int* __restrict__ batch)
{
    int i = blockIdx.x * blockDim.x + threadIdx.x;
    if (i < NN) {
        int o = g_off[i] + g_part[i / SCAN_B];
        g_off[i] = o;
        g_cur[i] = o;
        g_dinv[i] = rsqrtf((float)(g_edeg[i] + 1));   // +1 self loop
    }
    if (i == 0) g_off[NN] = EE;

    int start = i * 16;
    if (start < NN) {
        int end = min(start + 16, NN);
        int curg = batch[start], acc = 0;
        for (int n = start; n < end; n++) {
            int gi = batch[n];
            if (gi != curg) { atomicAdd(&g_cnt[curg], acc); curg = gi; acc = 0; }
            acc++;
        }
        atomicAdd(&g_cnt[curg], acc);
    }
}

// ---------------- bucket edges by dst ----------------
__global__ void k_bucket(const int* __restrict__ src, const int* __restrict__ dst)
{
    int e = blockIdx.x * blockDim.x + threadIdx.x;
    if (e >= EE) return;
    int d = dst[e];
    int pos = atomicAdd(&g_cur[d], 1);
    g_esrc[pos] = src[e];
}

// ---------------- fused GEMM: HL = (scale*X + dconst) @ W^T  -------------
__global__ __launch_bounds__(128) void k_gemm(const float* __restrict__ X,
                                              const float* __restrict__ W)
{
    __shared__ __align__(16) float  sW[HH * HH];   // sW[k*64+o] = W[o][k]*scale[k]
    __shared__ float4 sX[128 * 17];
    int tid  = threadIdx.x;
    int base = blockIdx.x * 128;

    for (int i = tid; i < HH * HH; i += 128) {
        int o = i >> 6, k = i & 63;
        sW[k * HH + o] = W[i] * g_scale[k];
    }
    for (int i = tid; i < 128 * 16; i += 128) {
        int r = i >> 4, c4 = i & 15;
        int node = base + r;
        float4 v = make_float4(0.f, 0.f, 0.f, 0.f);
        if (node < NN) v = ((const float4*)X)[(size_t)node * 16 + c4];
        sX[r * 17 + c4] = v;
    }
    __syncthreads();

    int oh = tid & 1;
    int pn = tid >> 1;
    int n0 = base + pn, n1 = base + 64 + pn;

    ull a0[16], a1[16];
    const ulonglong2* cv = (const ulonglong2*)(g_cvec + oh * 32);
#pragma unroll
    for (int j = 0; j < 8; j++) {
        ulonglong2 c = cv[j];
        a0[2*j] = c.x; a0[2*j+1] = c.y;
        a1[2*j] = c.x; a1[2*j+1] = c.y;
    }

#pragma unroll 4
    for (int k4 = 0; k4 < 16; k4++) {
        float4 xv0 = sX[pn * 17 + k4];
        float4 xv1 = sX[(pn + 64) * 17 + k4];
#pragma unroll
        for (int kk = 0; kk < 4; kk++) {
            float xs0 = (kk == 0) ? xv0.x : (kk == 1) ? xv0.y : (kk == 2) ? xv0.z : xv0.w;
            float xs1 = (kk == 0) ? xv1.x : (kk == 1) ? xv1.y : (kk == 2) ? xv1.z : xv1.w;
            ull xx0 = dup2(xs0);
            ull xx1 = dup2(xs1);
            const ulonglong2* wr = (const ulonglong2*)(sW + (k4 * 4 + kk) * HH + oh * 32);
#pragma unroll
            for (int j = 0; j < 8; j++) {
                ulonglong2 w = wr[j];
                a0[2*j]   = fma2(xx0, w.x, a0[2*j]);
                a0[2*j+1] = fma2(xx0, w.y, a0[2*j+1]);
                a1[2*j]   = fma2(xx1, w.x, a1[2*j]);
                a1[2*j+1] = fma2(xx1, w.y, a1[2*j+1]);
            }
        }
    }

    if (n0 < NN) {
        float d = g_dinv[n0];
        float4* hl = (float4*)(g_hl + (size_t)n0 * HH + oh * 32);
#pragma unroll
        for (int j = 0; j < 8; j++) {
            float2 lo = unp2(a0[2*j]), hi = unp2(a0[2*j+1]);
            hl[j] = make_float4(lo.x * d, lo.y * d, hi.x * d, hi.y * d);
        }
    }
    if (n1 < NN) {
        float d = g_dinv[n1];
        float4* hl = (float4*)(g_hl + (size_t)n1 * HH + oh * 32);
#pragma unroll
        for (int j = 0; j < 8; j++) {
            float2 lo = unp2(a1[2*j]), hi = unp2(a1[2*j+1]);
            hl[j] = make_float4(lo.x * d, lo.y * d, hi.x * d, hi.y * d);
        }
    }
}

// ---- fused pull-aggregate + bias + relu + BN stats + raw segment pool ----
// 256 threads = 16 groups of 16; one node per group, one float4 per thread.
// Neighbor loop: chunks of 16, two batches of 8 UNCONDITIONAL loads (pad idx 0
// -> broadcast line, cheap), adds predicated. MLP=8 per batch.
__global__ __launch_bounds__(256) void k_agg(const float* __restrict__ b,
                                             const int* __restrict__ batch,
                                             float* __restrict__ pool, int layer)
{
    int tid = threadIdx.x;
    int grp = tid >> 4;
    int q   = tid & 15;
    int node = blockIdx.x * 16 + grp;      // grid is exactly NN/16

    unsigned mask = 0xFFFFu << (((tid & 31) >> 4) << 4);

    const float4* hl4 = (const float4*)g_hl;
    float4 acc = hl4[(size_t)node * 16 + q];   // self-loop term

    int beg = g_off[node], end = g_off[node + 1];
    for (int p = beg; p < end; p += 16) {
        int rem = end - p;                                  // group-uniform
        int idx = (q < rem) ? g_esrc[p + q] : 0;

        float4 v[8];
#pragma unroll
        for (int j = 0; j < 8; j++) {
            int s = __shfl_sync(mask, idx, j, 16);
            v[j] = hl4[(size_t)s * 16 + q];
        }
#pragma unroll
        for (int j = 0; j < 8; j++) {
            if (j < rem) { acc.x += v[j].x; acc.y += v[j].y; acc.z += v[j].z; acc.w += v[j].w; }
        }
        if (rem > 8) {
#pragma unroll
            for (int j = 0; j < 8; j++) {
                int s = __shfl_sync(mask, idx, 8 + j, 16);
                v[j] = hl4[(size_t)s * 16 + q];
            }
#pragma unroll
            for (int j = 0; j < 8; j++) {
                if (8 + j < rem) { acc.x += v[j].x; acc.y += v[j].y; acc.z += v[j].z; acc.w += v[j].w; }
            }
        }
    }

    float di = g_dinv[node];
    float4 bv = ((const float4*)b)[q];
    float4 y;
    y.x = fmaxf(fmaf(acc.x, di, bv.x), 0.f);
    y.y = fmaxf(fmaf(acc.y, di, bv.y), 0.f);
    y.z = fmaxf(fmaf(acc.z, di, bv.z), 0.f);
    y.w = fmaxf(fmaf(acc.w, di, bv.w), 0.f);
    ((float4*)g_out)[(size_t)node * 16 + q] = y;

    __shared__ float sY[16][HH + 4];
    __shared__ int   sB[16];
    sY[grp][q*4+0] = y.x;
    sY[grp][q*4+1] = y.y;
    sY[grp][q*4+2] = y.z;
    sY[grp][q*4+3] = y.w;
    if (q == 0) sB[grp] = batch[node];
    __syncthreads();

    if (tid < HH) {
        int c = tid;
        float s = 0.f, s2 = 0.f, pacc = 0.f;
        int curg = sB[0];
#pragma unroll
        for (int g2 = 0; g2 < 16; g2++) {
            float v = sY[g2][c];
            s += v;
            s2 = fmaf(v, v, s2);
            int gi = sB[g2];
            if (gi != curg) {
                atomicAdd(&pool[(size_t)curg * 192 + c], pacc);
                curg = gi; pacc = 0.f;
            }
            pacc += v;
        }
        atomicAdd(&pool[(size_t)curg * 192 + c], pacc);
        atomicAdd(&g_sum  [layer * HH + c], s);
        atomicAdd(&g_sumsq[layer * HH + c], s2);
    }
}

// ---------------- BN params + fused constant vector for next GEMM --------
__global__ void k_bn(const float* __restrict__ g, const float* __restrict__ beta,
                     const float* __restrict__ Wnext, int layer)
{
    int c = threadIdx.x;   // 64
    float m   = g_sum  [layer * HH + c] * (1.0f / NN);
    float var = g_sumsq[layer * HH + c] * (1.0f / NN) - m * m;
    float r  = rsqrtf(var + BN_EPS);
    float sc = g[c] * r;
    float dc = beta[c] - m * sc;
    g_scale[c]  = sc;
    g_dconst[c] = dc;

    __shared__ float sdc[HH];
    sdc[c] = dc;
    __syncthreads();
    if (Wnext) {
        float acc = 0.f;
#pragma unroll 8
        for (int k = 0; k < HH; k++) acc = fmaf(sdc[k], Wnext[c * HH + k], acc);
        g_cvec[c] = acc;
    }
}

// ---------------- pooled fixup: pool = scale*raw + cnt*dconst -------------
__global__ void k_poolfin(float* __restrict__ pool)
{
    int idx = blockIdx.x * blockDim.x + threadIdx.x;
    if (idx >= GG * HH) return;
    int gph = idx >> 6, c = idx & 63;
    float raw = pool[(size_t)gph * 192 + c];
    pool[(size_t)gph * 192 + c] = g_scale[c] * raw + (float)g_cnt[gph] * g_dconst[c];
}

// ---- layer-2 finale: pool fixup + BN-applied h output, fused ------------
__global__ void k_fin(float* __restrict__ pool, float* __restrict__ outh)
{
    int idx = blockIdx.x * blockDim.x + threadIdx.x;

    if (idx < GG * HH) {
        int gph = idx >> 6, c = idx & 63;
        float raw = pool[(size_t)gph * 192 + c];
        pool[(size_t)gph * 192 + c] = g_scale[c] * raw + (float)g_cnt[gph] * g_dconst[c];
    }

    if (idx < NN * 16) {
        float4 v = ((const float4*)g_out)[idx];
        int c = (idx & 15) * 4;
        v.x = v.x * g_scale[c]     + g_dconst[c];
        v.y = v.y * g_scale[c + 1] + g_dconst[c + 1];
        v.z = v.z * g_scale[c + 2] + g_dconst[c + 2];
        v.w = v.w * g_scale[c + 3] + g_dconst[c + 3];
        ((float4*)outh)[idx] = v;
    }
}

// ---------------- host launcher ----------------
extern "C" void kernel_launch(void* const* d_in, const int* in_sizes, int n_in,
                              void* d_out, int out_size)
{
    const float* x     = (const float*)d_in[0];
    const int*   eidx  = (const int*)  d_in[1];
    const int*   batch = (const int*)  d_in[2];
    const int*   src   = eidx;
    const int*   dst   = eidx + EE;

    const float* W[3]   = { (const float*)d_in[3],  (const float*)d_in[7],  (const float*)d_in[11] };
    const float* b[3]   = { (const float*)d_in[4],  (const float*)d_in[8],  (const float*)d_in[12] };
    const float* gam[3] = { (const float*)d_in[5],  (const float*)d_in[9],  (const float*)d_in[13] };
    const float* bet[3] = { (const float*)d_in[6],  (const float*)d_in[10], (const float*)d_in[14] };

    float* out = (float*)d_out;

    float* d_relu;
    cudaGetSymbolAddress((void**)&d_relu, g_out);

    // setup: degrees, CSR (scan fused with dinv + graph counts)
    k_init  <<<(NN + 255) / 256, 256>>>(out);
    k_deg   <<<(EE + 255) / 256, 256>>>(dst);
    k_scan1 <<<NBLK, SCAN_B>>>();
    k_scan2 <<<1, 128>>>();
    k_scan3 <<<(NN + 255) / 256, 256>>>(batch);
    k_bucket<<<(EE + 255) / 256, 256>>>(src, dst);

    const float* layer_in = x;
    for (int l = 0; l < 3; l++) {
        k_gemm<<<(NN + 127) / 128, 128>>>(layer_in, W[l]);
        k_agg <<<NN / 16, 256>>>(b[l], batch, out + l * 64, l);
        k_bn  <<<1, 64>>>(gam[l], bet[l], (l < 2) ? W[l + 1] : nullptr, l);
        if (l < 2)
            k_poolfin<<<(GG * HH + 255) / 256, 256>>>(out + l * 64);
        layer_in = d_relu;
    }
    k_fin<<<(NN * 16 + 255) / 256, 256>>>(out + 2 * 64, out + (size_t)GG * 192);
}

// round 12
// speedup vs baseline: 1.6033x; 1.0517x over previous
#include <cuda_runtime.h>
#include <cuda_bf16.h>

#define NN 100000
#define EE 1000000
#define HH 64
#define GG 512
#define BN_EPS 1e-5f

#define SCAN_B 1024
#define NBLK ((NN + SCAN_B - 1) / SCAN_B)   // 98

typedef unsigned long long ull;

// ---------------- device scratch (no allocations allowed) ----------------
__device__ __align__(16) float g_hl [NN * HH];   // lin output (NOT dinv-scaled)
__device__ __align__(16) float g_out[NN * HH];   // relu(agg+bias) raw layer output
__device__ float g_dinv[NN];
__device__ int   g_edeg[NN];        // edge-only in-degree
__device__ int   g_off [NN + 1];    // CSR offsets
__device__ int   g_cur [NN];        // bucket cursors
__device__ int   g_esrc[EE];        // src index bucketed by dst
__device__ int   g_part[NBLK];      // scan partials
__device__ int   g_cnt [GG];
__device__ float g_sum  [3 * HH];
__device__ float g_sumsq[3 * HH];
__device__ __align__(16) float g_scale [HH];      // rolling: BN scale of previous layer
__device__ __align__(16) float g_dconst[HH];      // rolling: BN shift of previous layer
__device__ __align__(16) float g_cvec  [HH];      // dconst @ W_next^T
__device__ __align__(16) float g_scaleA [3 * HH]; // archived per-layer BN params
__device__ __align__(16) float g_dconstA[3 * HH];

// ---------------- f32x2 helpers ----------------
__device__ __forceinline__ ull fma2(ull a, ull b, ull c) {
    ull d;
    asm("fma.rn.f32x2 %0, %1, %2, %3;" : "=l"(d) : "l"(a), "l"(b), "l"(c));
    return d;
}
__device__ __forceinline__ ull dup2(float x) {
    ull d;
    unsigned r = __float_as_uint(x);
    asm("mov.b64 %0, {%1, %1};" : "=l"(d) : "r"(r));
    return d;
}
__device__ __forceinline__ float2 unp2(ull a) {
    unsigned lo, hi;
    asm("mov.b64 {%0, %1}, %2;" : "=r"(lo), "=r"(hi) : "l"(a));
    return make_float2(__uint_as_float(lo), __uint_as_float(hi));
}

// ---------------- init ----------------
__global__ void k_init(float* __restrict__ dout)
{
    int i = blockIdx.x * blockDim.x + threadIdx.x;
    if (i < NN)            g_edeg[i] = 0;
    if (i < GG * 3 * HH)   dout[i]  = 0.0f;       // pooled region
    if (i < 3 * HH) { g_sum[i] = 0.0f; g_sumsq[i] = 0.0f; }
    if (i < HH)     { g_scale[i] = 1.0f; g_dconst[i] = 0.0f; g_cvec[i] = 0.0f; }
    if (i < GG)       g_cnt[i] = 0;
}

// ---------------- edge-only in-degree over dst ----------------
__global__ void k_deg(const int* __restrict__ dst)
{
    int e = blockIdx.x * blockDim.x + threadIdx.x;
    if (e < EE) atomicAdd(&g_edeg[dst[e]], 1);
}

// ---------------- exclusive scan of g_edeg -> g_off ----------------------
__global__ __launch_bounds__(SCAN_B) void k_scan1()
{
    __shared__ int sh[SCAN_B];
    int t = threadIdx.x;
    int i = blockIdx.x * SCAN_B + t;
    int v = (i < NN) ? g_edeg[i] : 0;
    sh[t] = v;
    __syncthreads();
    int val = v;
    for (int d = 1; d < SCAN_B; d <<= 1) {
        int add = (t >= d) ? sh[t - d] : 0;
        __syncthreads();
        val += add;
        sh[t] = val;
        __syncthreads();
    }
    if (i < NN) g_off[i] = val - v;                // local exclusive
    if (t == SCAN_B - 1) g_part[blockIdx.x] = val; // block total
}

// parallel exclusive scan of 98 block totals
__global__ __launch_bounds__(128) void k_scan2()
{
    __shared__ int warpSum[4];
    int t = threadIdx.x;
    int lane = t & 31, w = t >> 5;
    int v = (t < NBLK) ? g_part[t] : 0;
    int inc = v;
#pragma unroll
    for (int d = 1; d < 32; d <<= 1) {
        int n = __shfl_up_sync(0xFFFFFFFFu, inc, d);
        if (lane >= d) inc += n;
    }
    if (lane == 31) warpSum[w] = inc;
    __syncthreads();
    int base = 0;
    for (int j = 0; j < w; j++) base += warpSum[j];
    if (t < NBLK) g_part[t] = base + inc - v;      // exclusive
}

// scan finalize + dinv + per-graph node counts (fused)
__global__ void k_scan3(const int* __restrict__ batch)
{
    int i = blockIdx.x * blockDim.x + threadIdx.x;
    if (i < NN) {
        int o = g_off[i] + g_part[i / SCAN_B];
        g_off[i] = o;
        g_cur[i] = o;
        g_dinv[i] = rsqrtf((float)(g_edeg[i] + 1));   // +1 self loop
    }
    if (i == 0) g_off[NN] = EE;

    int start = i * 16;
    if (start < NN) {
        int end = min(start + 16, NN);
        int curg = batch[start], acc = 0;
        for (int n = start; n < end; n++) {
            int gi = batch[n];
            if (gi != curg) { atomicAdd(&g_cnt[curg], acc); curg = gi; acc = 0; }
            acc++;
        }
        atomicAdd(&g_cnt[curg], acc);
    }
}

// ---------------- bucket edges by dst ----------------
__global__ void k_bucket(const int* __restrict__ src, const int* __restrict__ dst)
{
    int e = blockIdx.x * blockDim.x + threadIdx.x;
    if (e >= EE) return;
    int d = dst[e];
    int pos = atomicAdd(&g_cur[d], 1);
    g_esrc[pos] = src[e];
}

// ---------------- fused GEMM: HL = (scale*X + dconst) @ W^T  -------------
// = X @ (W*scale)^T + cvec.  Writes g_hl (no dinv — deferred into k_agg).
__global__ __launch_bounds__(128) void k_gemm(const float* __restrict__ X,
                                              const float* __restrict__ W)
{
    __shared__ __align__(16) float  sW[HH * HH];   // sW[k*64+o] = W[o][k]*scale[k]
    __shared__ float4 sX[128 * 17];
    int tid  = threadIdx.x;
    int base = blockIdx.x * 128;

    for (int i = tid; i < HH * HH; i += 128) {
        int o = i >> 6, k = i & 63;
        sW[k * HH + o] = W[i] * g_scale[k];
    }
    for (int i = tid; i < 128 * 16; i += 128) {
        int r = i >> 4, c4 = i & 15;
        int node = base + r;
        float4 v = make_float4(0.f, 0.f, 0.f, 0.f);
        if (node < NN) v = ((const float4*)X)[(size_t)node * 16 + c4];
        sX[r * 17 + c4] = v;
    }
    __syncthreads();

    int oh = tid & 1;
    int pn = tid >> 1;
    int n0 = base + pn, n1 = base + 64 + pn;

    ull a0[16], a1[16];
    const ulonglong2* cv = (const ulonglong2*)(g_cvec + oh * 32);
#pragma unroll
    for (int j = 0; j < 8; j++) {
        ulonglong2 c = cv[j];
        a0[2*j] = c.x; a0[2*j+1] = c.y;
        a1[2*j] = c.x; a1[2*j+1] = c.y;
    }

#pragma unroll 4
    for (int k4 = 0; k4 < 16; k4++) {
        float4 xv0 = sX[pn * 17 + k4];
        float4 xv1 = sX[(pn + 64) * 17 + k4];
#pragma unroll
        for (int kk = 0; kk < 4; kk++) {
            float xs0 = (kk == 0) ? xv0.x : (kk == 1) ? xv0.y : (kk == 2) ? xv0.z : xv0.w;
            float xs1 = (kk == 0) ? xv1.x : (kk == 1) ? xv1.y : (kk == 2) ? xv1.z : xv1.w;
            ull xx0 = dup2(xs0);
            ull xx1 = dup2(xs1);
            const ulonglong2* wr = (const ulonglong2*)(sW + (k4 * 4 + kk) * HH + oh * 32);
#pragma unroll
            for (int j = 0; j < 8; j++) {
                ulonglong2 w = wr[j];
                a0[2*j]   = fma2(xx0, w.x, a0[2*j]);
                a0[2*j+1] = fma2(xx0, w.y, a0[2*j+1]);
                a1[2*j]   = fma2(xx1, w.x, a1[2*j]);
                a1[2*j+1] = fma2(xx1, w.y, a1[2*j+1]);
            }
        }
    }

    if (n0 < NN) {
        float4* hl = (float4*)(g_hl + (size_t)n0 * HH + oh * 32);
#pragma unroll
        for (int j = 0; j < 8; j++) {
            float2 lo = unp2(a0[2*j]), hi = unp2(a0[2*j+1]);
            hl[j] = make_float4(lo.x, lo.y, hi.x, hi.y);
        }
    }
    if (n1 < NN) {
        float4* hl = (float4*)(g_hl + (size_t)n1 * HH + oh * 32);
#pragma unroll
        for (int j = 0; j < 8; j++) {
            float2 lo = unp2(a1[2*j]), hi = unp2(a1[2*j+1]);
            hl[j] = make_float4(lo.x, lo.y, hi.x, hi.y);
        }
    }
}

// ---- fused pull-aggregate + bias + relu + BN stats + raw segment pool ----
// 256 threads = 16 groups of 16; one node per group, one float4 per thread.
// dinv applied here: acc = dinv[d]*hl[d] + sum_s dinv[s]*hl[s]; y=relu(dinv[d]*acc+b)
__global__ __launch_bounds__(256) void k_agg(const float* __restrict__ b,
                                             const int* __restrict__ batch,
                                             float* __restrict__ pool, int layer)
{
    int tid = threadIdx.x;
    int grp = tid >> 4;
    int q   = tid & 15;
    int node = blockIdx.x * 16 + grp;      // grid is exactly NN/16

    unsigned mask = 0xFFFFu << (((tid & 31) >> 4) << 4);

    const float4* hl4 = (const float4*)g_hl;
    float di = g_dinv[node];
    float4 vs = hl4[(size_t)node * 16 + q];
    float4 acc = make_float4(vs.x * di, vs.y * di, vs.z * di, vs.w * di);

    int beg = g_off[node], end = g_off[node + 1];
    for (int p = beg; p < end; p += 16) {
        int rem = end - p;                                  // group-uniform
        int idx = (q < rem) ? g_esrc[p + q] : 0;
        float dsl = g_dinv[idx];

        float4 v[8];
        float  w[8];
#pragma unroll
        for (int j = 0; j < 8; j++) {
            int s = __shfl_sync(mask, idx, j, 16);
            w[j]  = __shfl_sync(mask, dsl, j, 16);
            v[j]  = hl4[(size_t)s * 16 + q];
        }
#pragma unroll
        for (int j = 0; j < 8; j++) {
            if (j < rem) {
                acc.x = fmaf(v[j].x, w[j], acc.x);
                acc.y = fmaf(v[j].y, w[j], acc.y);
                acc.z = fmaf(v[j].z, w[j], acc.z);
                acc.w = fmaf(v[j].w, w[j], acc.w);
            }
        }
        if (rem > 8) {
#pragma unroll
            for (int j = 0; j < 8; j++) {
                int s = __shfl_sync(mask, idx, 8 + j, 16);
                w[j]  = __shfl_sync(mask, dsl, 8 + j, 16);
                v[j]  = hl4[(size_t)s * 16 + q];
            }
#pragma unroll
            for (int j = 0; j < 8; j++) {
                if (8 + j < rem) {
                    acc.x = fmaf(v[j].x, w[j], acc.x);
                    acc.y = fmaf(v[j].y, w[j], acc.y);
                    acc.z = fmaf(v[j].z, w[j], acc.z);
                    acc.w = fmaf(v[j].w, w[j], acc.w);
                }
            }
        }
    }

    float4 bv = ((const float4*)b)[q];
    float4 y;
    y.x = fmaxf(fmaf(acc.x, di, bv.x), 0.f);
    y.y = fmaxf(fmaf(acc.y, di, bv.y), 0.f);
    y.z = fmaxf(fmaf(acc.z, di, bv.z), 0.f);
    y.w = fmaxf(fmaf(acc.w, di, bv.w), 0.f);
    ((float4*)g_out)[(size_t)node * 16 + q] = y;

    __shared__ float sY[16][HH + 4];
    __shared__ int   sB[16];
    sY[grp][q*4+0] = y.x;
    sY[grp][q*4+1] = y.y;
    sY[grp][q*4+2] = y.z;
    sY[grp][q*4+3] = y.w;
    if (q == 0) sB[grp] = batch[node];
    __syncthreads();

    if (tid < HH) {
        int c = tid;
        float s = 0.f, s2 = 0.f, pacc = 0.f;
        int curg = sB[0];
#pragma unroll
        for (int g2 = 0; g2 < 16; g2++) {
            float v = sY[g2][c];
            s += v;
            s2 = fmaf(v, v, s2);
            int gi = sB[g2];
            if (gi != curg) {
                atomicAdd(&pool[(size_t)curg * 192 + c], pacc);
                curg = gi; pacc = 0.f;
            }
            pacc += v;
        }
        atomicAdd(&pool[(size_t)curg * 192 + c], pacc);
        atomicAdd(&g_sum  [layer * HH + c], s);
        atomicAdd(&g_sumsq[layer * HH + c], s2);
    }
}

// ---------------- BN params + fused constant vector for next GEMM --------
__global__ void k_bn(const float* __restrict__ g, const float* __restrict__ beta,
                     const float* __restrict__ Wnext, int layer)
{
    int c = threadIdx.x;   // 64
    float m   = g_sum  [layer * HH + c] * (1.0f / NN);
    float var = g_sumsq[layer * HH + c] * (1.0f / NN) - m * m;
    float r  = rsqrtf(var + BN_EPS);
    float sc = g[c] * r;
    float dc = beta[c] - m * sc;
    g_scale[c]  = sc;
    g_dconst[c] = dc;
    g_scaleA [layer * HH + c] = sc;
    g_dconstA[layer * HH + c] = dc;

    __shared__ float sdc[HH];
    sdc[c] = dc;
    __syncthreads();
    if (Wnext) {
        float acc = 0.f;
#pragma unroll 8
        for (int k = 0; k < HH; k++) acc = fmaf(sdc[k], Wnext[c * HH + k], acc);
        g_cvec[c] = acc;
    }
}

// ---- finale: all 3 pool fixups + BN-applied final h output --------------
__global__ void k_fin(float* __restrict__ out, float* __restrict__ outh)
{
    int idx = blockIdx.x * blockDim.x + threadIdx.x;

    if (idx < GG * HH) {
        int gph = idx >> 6, c = idx & 63;
        float cntf = (float)g_cnt[gph];
#pragma unroll
        for (int l = 0; l < 3; l++) {
            float* p = out + (size_t)gph * 192 + l * 64 + c;
            float raw = *p;
            *p = g_scaleA[l * HH + c] * raw + cntf * g_dconstA[l * HH + c];
        }
    }

    if (idx < NN * 16) {
        float4 v = ((const float4*)g_out)[idx];
        int c = (idx & 15) * 4;
        v.x = v.x * g_scaleA[2*HH + c]     + g_dconstA[2*HH + c];
        v.y = v.y * g_scaleA[2*HH + c + 1] + g_dconstA[2*HH + c + 1];
        v.z = v.z * g_scaleA[2*HH + c + 2] + g_dconstA[2*HH + c + 2];
        v.w = v.w * g_scaleA[2*HH + c + 3] + g_dconstA[2*HH + c + 3];
        ((float4*)outh)[idx] = v;
    }
}

// ---------------- host launcher ----------------
extern "C" void kernel_launch(void* const* d_in, const int* in_sizes, int n_in,
                              void* d_out, int out_size)
{
    const float* x     = (const float*)d_in[0];
    const int*   eidx  = (const int*)  d_in[1];
    const int*   batch = (const int*)  d_in[2];
    const int*   src   = eidx;
    const int*   dst   = eidx + EE;

    const float* W[3]   = { (const float*)d_in[3],  (const float*)d_in[7],  (const float*)d_in[11] };
    const float* b[3]   = { (const float*)d_in[4],  (const float*)d_in[8],  (const float*)d_in[12] };
    const float* gam[3] = { (const float*)d_in[5],  (const float*)d_in[9],  (const float*)d_in[13] };
    const float* bet[3] = { (const float*)d_in[6],  (const float*)d_in[10], (const float*)d_in[14] };

    float* out = (float*)d_out;

    float* d_relu;
    cudaGetSymbolAddress((void**)&d_relu, g_out);

    // lazily create side stream + events on the first (non-captured) call
    static cudaStream_t s2 = nullptr;
    static cudaEvent_t  evFork = nullptr, evJoin = nullptr;
    if (!s2) {
        cudaStreamCreateWithFlags(&s2, cudaStreamNonBlocking);
        cudaEventCreateWithFlags(&evFork, cudaEventDisableTiming);
        cudaEventCreateWithFlags(&evJoin, cudaEventDisableTiming);
    }

    // init, then fork: layer-0 GEMM (independent of graph structure) on s2
    k_init<<<(NN + 255) / 256, 256>>>(out);
    cudaEventRecord(evFork, 0);
    cudaStreamWaitEvent(s2, evFork, 0);
    k_gemm<<<(NN + 127) / 128, 128, 0, s2>>>(x, W[0]);
    cudaEventRecord(evJoin, s2);

    // CSR build on the main stream (overlaps gemm0)
    k_deg   <<<(EE + 255) / 256, 256>>>(dst);
    k_scan1 <<<NBLK, SCAN_B>>>();
    k_scan2 <<<1, 128>>>();
    k_scan3 <<<(NN + 255) / 256, 256>>>(batch);
    k_bucket<<<(EE + 255) / 256, 256>>>(src, dst);
    cudaStreamWaitEvent(0, evJoin, 0);

    for (int l = 0; l < 3; l++) {
        if (l > 0)
            k_gemm<<<(NN + 127) / 128, 128>>>(d_relu, W[l]);
        k_agg<<<NN / 16, 256>>>(b[l], batch, out + l * 64, l);
        k_bn <<<1, 64>>>(gam[l], bet[l], (l < 2) ? W[l + 1] : nullptr, l);
    }
    k_fin<<<(NN * 16 + 255) / 256, 256>>>(out, out + (size_t)GG * 192);
}

// round 13
// speedup vs baseline: 1.7352x; 1.0823x over previous
#include <cuda_runtime.h>
#include <cuda_fp16.h>
#include <cuda_bf16.h>

#define NN 100000
#define EE 1000000
#define HH 64
#define GG 512
#define BN_EPS 1e-5f

#define SCAN_B 1024
#define NBLK ((NN + SCAN_B - 1) / SCAN_B)   // 98

typedef unsigned long long ull;

// ---------------- device scratch (no allocations allowed) ----------------
__device__ __align__(16) __half g_hl16[NN * HH]; // lin output (fp16 payload, NOT dinv-scaled)
__device__ __align__(16) float  g_out[NN * HH];  // relu(agg+bias) raw layer output
__device__ float g_dinv[NN];
__device__ int   g_edeg[NN];        // edge-only in-degree
__device__ int   g_off [NN + 1];    // CSR offsets
__device__ int   g_cur [NN];        // bucket cursors
__device__ int   g_esrc[EE];        // src index bucketed by dst
__device__ int   g_part[NBLK];      // scan partials
__device__ int   g_cnt [GG];
__device__ float g_sum  [3 * HH];
__device__ float g_sumsq[3 * HH];
__device__ __align__(16) float g_scale [HH];      // rolling: BN scale of previous layer
__device__ __align__(16) float g_dconst[HH];      // rolling: BN shift of previous layer
__device__ __align__(16) float g_cvec  [HH];      // dconst @ W_next^T
__device__ __align__(16) float g_scaleA [3 * HH]; // archived per-layer BN params
__device__ __align__(16) float g_dconstA[3 * HH];

// ---------------- f32x2 helpers ----------------
__device__ __forceinline__ ull fma2(ull a, ull b, ull c) {
    ull d;
    asm("fma.rn.f32x2 %0, %1, %2, %3;" : "=l"(d) : "l"(a), "l"(b), "l"(c));
    return d;
}
__device__ __forceinline__ ull dup2(float x) {
    ull d;
    unsigned r = __float_as_uint(x);
    asm("mov.b64 %0, {%1, %1};" : "=l"(d) : "r"(r));
    return d;
}
__device__ __forceinline__ float2 unp2(ull a) {
    unsigned lo, hi;
    asm("mov.b64 {%0, %1}, %2;" : "=r"(lo), "=r"(hi) : "l"(a));
    return make_float2(__uint_as_float(lo), __uint_as_float(hi));
}
__device__ __forceinline__ float4 h4f4(uint2 u) {
    __half2 a = *reinterpret_cast<__half2*>(&u.x);
    __half2 b = *reinterpret_cast<__half2*>(&u.y);
    float2 fa = __half22float2(a), fb = __half22float2(b);
    return make_float4(fa.x, fa.y, fb.x, fb.y);
}

// ---------------- init ----------------
__global__ void k_init(float* __restrict__ dout)
{
    int i = blockIdx.x * blockDim.x + threadIdx.x;
    if (i < NN)            g_edeg[i] = 0;
    if (i < GG * 3 * HH)   dout[i]  = 0.0f;       // pooled region
    if (i < 3 * HH) { g_sum[i] = 0.0f; g_sumsq[i] = 0.0f; }
    if (i < HH)     { g_scale[i] = 1.0f; g_dconst[i] = 0.0f; g_cvec[i] = 0.0f; }
    if (i < GG)       g_cnt[i] = 0;
}

// ---------------- edge-only in-degree over dst ----------------
__global__ void k_deg(const int* __restrict__ dst)
{
    int e = blockIdx.x * blockDim.x + threadIdx.x;
    if (e < EE) atomicAdd(&g_edeg[dst[e]], 1);
}

// ---------------- exclusive scan of g_edeg -> g_off ----------------------
__global__ __launch_bounds__(SCAN_B) void k_scan1()
{
    __shared__ int sh[SCAN_B];
    int t = threadIdx.x;
    int i = blockIdx.x * SCAN_B + t;
    int v = (i < NN) ? g_edeg[i] : 0;
    sh[t] = v;
    __syncthreads();
    int val = v;
    for (int d = 1; d < SCAN_B; d <<= 1) {
        int add = (t >= d) ? sh[t - d] : 0;
        __syncthreads();
        val += add;
        sh[t] = val;
        __syncthreads();
    }
    if (i < NN) g_off[i] = val - v;                // local exclusive
    if (t == SCAN_B - 1) g_part[blockIdx.x] = val; // block total
}

// parallel exclusive scan of 98 block totals
__global__ __launch_bounds__(128) void k_scan2()
{
    __shared__ int warpSum[4];
    int t = threadIdx.x;
    int lane = t & 31, w = t >> 5;
    int v = (t < NBLK) ? g_part[t] : 0;
    int inc = v;
#pragma unroll
    for (int d = 1; d < 32; d <<= 1) {
        int n = __shfl_up_sync(0xFFFFFFFFu, inc, d);
        if (lane >= d) inc += n;
    }
    if (lane == 31) warpSum[w] = inc;
    __syncthreads();
    int base = 0;
    for (int j = 0; j < w; j++) base += warpSum[j];
    if (t < NBLK) g_part[t] = base + inc - v;      // exclusive
}

// scan finalize + dinv + per-graph node counts (fused)
__global__ void k_scan3(const int* __restrict__ batch)
{
    int i = blockIdx.x * blockDim.x + threadIdx.x;
    if (i < NN) {
        int o = g_off[i] + g_part[i / SCAN_B];
        g_off[i] = o;
        g_cur[i] = o;
        g_dinv[i] = rsqrtf((float)(g_edeg[i] + 1));   // +1 self loop
    }
    if (i == 0) g_off[NN] = EE;

    int start = i * 16;
    if (start < NN) {
        int end = min(start + 16, NN);
        int curg = batch[start], acc = 0;
        for (int n = start; n < end; n++) {
            int gi = batch[n];
            if (gi != curg) { atomicAdd(&g_cnt[curg], acc); curg = gi; acc = 0; }
            acc++;
        }
        atomicAdd(&g_cnt[curg], acc);
    }
}

// ---------------- bucket edges by dst ----------------
__global__ void k_bucket(const int* __restrict__ src, const int* __restrict__ dst)
{
    int e = blockIdx.x * blockDim.x + threadIdx.x;
    if (e >= EE) return;
    int d = dst[e];
    int pos = atomicAdd(&g_cur[d], 1);
    g_esrc[pos] = src[e];
}

// ---------------- fused GEMM: HL = (scale*X + dconst) @ W^T  -------------
// = X @ (W*scale)^T + cvec.  Writes g_hl16 (fp16; dinv deferred into k_agg).
__global__ __launch_bounds__(128) void k_gemm(const float* __restrict__ X,
                                              const float* __restrict__ W)
{
    __shared__ __align__(16) float  sW[HH * HH];   // sW[k*64+o] = W[o][k]*scale[k]
    __shared__ float4 sX[128 * 17];
    int tid  = threadIdx.x;
    int base = blockIdx.x * 128;

    for (int i = tid; i < HH * HH; i += 128) {
        int o = i >> 6, k = i & 63;
        sW[k * HH + o] = W[i] * g_scale[k];
    }
    for (int i = tid; i < 128 * 16; i += 128) {
        int r = i >> 4, c4 = i & 15;
        int node = base + r;
        float4 v = make_float4(0.f, 0.f, 0.f, 0.f);
        if (node < NN) v = ((const float4*)X)[(size_t)node * 16 + c4];
        sX[r * 17 + c4] = v;
    }
    __syncthreads();

    int oh = tid & 1;
    int pn = tid >> 1;
    int n0 = base + pn, n1 = base + 64 + pn;

    ull a0[16], a1[16];
    const ulonglong2* cv = (const ulonglong2*)(g_cvec + oh * 32);
#pragma unroll
    for (int j = 0; j < 8; j++) {
        ulonglong2 c = cv[j];
        a0[2*j] = c.x; a0[2*j+1] = c.y;
        a1[2*j] = c.x; a1[2*j+1] = c.y;
    }

#pragma unroll 4
    for (int k4 = 0; k4 < 16; k4++) {
        float4 xv0 = sX[pn * 17 + k4];
        float4 xv1 = sX[(pn + 64) * 17 + k4];
#pragma unroll
        for (int kk = 0; kk < 4; kk++) {
            float xs0 = (kk == 0) ? xv0.x : (kk == 1) ? xv0.y : (kk == 2) ? xv0.z : xv0.w;
            float xs1 = (kk == 0) ? xv1.x : (kk == 1) ? xv1.y : (kk == 2) ? xv1.z : xv1.w;
            ull xx0 = dup2(xs0);
            ull xx1 = dup2(xs1);
            const ulonglong2* wr = (const ulonglong2*)(sW + (k4 * 4 + kk) * HH + oh * 32);
#pragma unroll
            for (int j = 0; j < 8; j++) {
                ulonglong2 w = wr[j];
                a0[2*j]   = fma2(xx0, w.x, a0[2*j]);
                a0[2*j+1] = fma2(xx0, w.y, a0[2*j+1]);
                a1[2*j]   = fma2(xx1, w.x, a1[2*j]);
                a1[2*j+1] = fma2(xx1, w.y, a1[2*j+1]);
            }
        }
    }

    // epilogue: convert 32 outputs to fp16 and store 64B
    if (n0 < NN) {
        uint2* hl = (uint2*)(g_hl16 + (size_t)n0 * HH + oh * 32);
#pragma unroll
        for (int j = 0; j < 8; j++) {
            float2 lo = unp2(a0[2*j]), hi = unp2(a0[2*j+1]);
            __half2 h0 = __float22half2_rn(lo);
            __half2 h1 = __float22half2_rn(hi);
            hl[j] = make_uint2(*(unsigned*)&h0, *(unsigned*)&h1);
        }
    }
    if (n1 < NN) {
        uint2* hl = (uint2*)(g_hl16 + (size_t)n1 * HH + oh * 32);
#pragma unroll
        for (int j = 0; j < 8; j++) {
            float2 lo = unp2(a1[2*j]), hi = unp2(a1[2*j+1]);
            __half2 h0 = __float22half2_rn(lo);
            __half2 h1 = __float22half2_rn(hi);
            hl[j] = make_uint2(*(unsigned*)&h0, *(unsigned*)&h1);
        }
    }
}

// ---- fused pull-aggregate + bias + relu + BN stats + raw segment pool ----
// 256 threads = 16 groups of 16; one node per group, 4 channels (8B fp16) per thread.
// acc(fp32) = dinv[d]*hl[d] + sum_s dinv[s]*hl[s];  y = relu(dinv[d]*acc + b)
__global__ __launch_bounds__(256) void k_agg(const float* __restrict__ b,
                                             const int* __restrict__ batch,
                                             float* __restrict__ pool, int layer)
{
    int tid = threadIdx.x;
    int grp = tid >> 4;
    int q   = tid & 15;
    int node = blockIdx.x * 16 + grp;      // grid is exactly NN/16

    unsigned mask = 0xFFFFu << (((tid & 31) >> 4) << 4);

    const uint2* hl2 = (const uint2*)g_hl16;   // 8B = 4 halves per element
    float di = g_dinv[node];
    float4 vs = h4f4(hl2[(size_t)node * 16 + q]);
    float4 acc = make_float4(vs.x * di, vs.y * di, vs.z * di, vs.w * di);

    int beg = g_off[node], end = g_off[node + 1];
    for (int p = beg; p < end; p += 16) {
        int rem = end - p;                                  // group-uniform
        int idx = (q < rem) ? g_esrc[p + q] : 0;
        float dsl = g_dinv[idx];

        uint2 v[8];
        float w[8];
#pragma unroll
        for (int j = 0; j < 8; j++) {
            int s = __shfl_sync(mask, idx, j, 16);
            w[j]  = __shfl_sync(mask, dsl, j, 16);
            v[j]  = hl2[(size_t)s * 16 + q];
        }
#pragma unroll
        for (int j = 0; j < 8; j++) {
            if (j < rem) {
                float4 f = h4f4(v[j]);
                acc.x = fmaf(f.x, w[j], acc.x);
                acc.y = fmaf(f.y, w[j], acc.y);
                acc.z = fmaf(f.z, w[j], acc.z);
                acc.w = fmaf(f.w, w[j], acc.w);
            }
        }
        if (rem > 8) {
#pragma unroll
            for (int j = 0; j < 8; j++) {
                int s = __shfl_sync(mask, idx, 8 + j, 16);
                w[j]  = __shfl_sync(mask, dsl, 8 + j, 16);
                v[j]  = hl2[(size_t)s * 16 + q];
            }
#pragma unroll
            for (int j = 0; j < 8; j++) {
                if (8 + j < rem) {
                    float4 f = h4f4(v[j]);
                    acc.x = fmaf(f.x, w[j], acc.x);
                    acc.y = fmaf(f.y, w[j], acc.y);
                    acc.z = fmaf(f.z, w[j], acc.z);
                    acc.w = fmaf(f.w, w[j], acc.w);
                }
            }
        }
    }

    float4 bv = ((const float4*)b)[q];
    float4 y;
    y.x = fmaxf(fmaf(acc.x, di, bv.x), 0.f);
    y.y = fmaxf(fmaf(acc.y, di, bv.y), 0.f);
    y.z = fmaxf(fmaf(acc.z, di, bv.z), 0.f);
    y.w = fmaxf(fmaf(acc.w, di, bv.w), 0.f);
    ((float4*)g_out)[(size_t)node * 16 + q] = y;

    __shared__ float sY[16][HH + 4];
    __shared__ int   sB[16];
    sY[grp][q*4+0] = y.x;
    sY[grp][q*4+1] = y.y;
    sY[grp][q*4+2] = y.z;
    sY[grp][q*4+3] = y.w;
    if (q == 0) sB[grp] = batch[node];
    __syncthreads();

    if (tid < HH) {
        int c = tid;
        float s = 0.f, s2 = 0.f, pacc = 0.f;
        int curg = sB[0];
#pragma unroll
        for (int g2 = 0; g2 < 16; g2++) {
            float v = sY[g2][c];
            s += v;
            s2 = fmaf(v, v, s2);
            int gi = sB[g2];
            if (gi != curg) {
                atomicAdd(&pool[(size_t)curg * 192 + c], pacc);
                curg = gi; pacc = 0.f;
            }
            pacc += v;
        }
        atomicAdd(&pool[(size_t)curg * 192 + c], pacc);
        atomicAdd(&g_sum  [layer * HH + c], s);
        atomicAdd(&g_sumsq[layer * HH + c], s2);
    }
}

// ---------------- BN params + fused constant vector for next GEMM --------
__global__ void k_bn(const float* __restrict__ g, const float* __restrict__ beta,
                     const float* __restrict__ Wnext, int layer)
{
    int c = threadIdx.x;   // 64
    float m   = g_sum  [layer * HH + c] * (1.0f / NN);
    float var = g_sumsq[layer * HH + c] * (1.0f / NN) - m * m;
    float r  = rsqrtf(var + BN_EPS);
    float sc = g[c] * r;
    float dc = beta[c] - m * sc;
    g_scale[c]  = sc;
    g_dconst[c] = dc;
    g_scaleA [layer * HH + c] = sc;
    g_dconstA[layer * HH + c] = dc;

    __shared__ float sdc[HH];
    sdc[c] = dc;
    __syncthreads();
    if (Wnext) {
        float acc = 0.f;
#pragma unroll 8
        for (int k = 0; k < HH; k++) acc = fmaf(sdc[k], Wnext[c * HH + k], acc);
        g_cvec[c] = acc;
    }
}

// ---- finale: all 3 pool fixups + BN-applied final h output --------------
__global__ void k_fin(float* __restrict__ out, float* __restrict__ outh)
{
    int idx = blockIdx.x * blockDim.x + threadIdx.x;

    if (idx < GG * HH) {
        int gph = idx >> 6, c = idx & 63;
        float cntf = (float)g_cnt[gph];
#pragma unroll
        for (int l = 0; l < 3; l++) {
            float* p = out + (size_t)gph * 192 + l * 64 + c;
            float raw = *p;
            *p = g_scaleA[l * HH + c] * raw + cntf * g_dconstA[l * HH + c];
        }
    }

    if (idx < NN * 16) {
        float4 v = ((const float4*)g_out)[idx];
        int c = (idx & 15) * 4;
        v.x = v.x * g_scaleA[2*HH + c]     + g_dconstA[2*HH + c];
        v.y = v.y * g_scaleA[2*HH + c + 1] + g_dconstA[2*HH + c + 1];
        v.z = v.z * g_scaleA[2*HH + c + 2] + g_dconstA[2*HH + c + 2];
        v.w = v.w * g_scaleA[2*HH + c + 3] + g_dconstA[2*HH + c + 3];
        ((float4*)outh)[idx] = v;
    }
}

// ---------------- host launcher ----------------
extern "C" void kernel_launch(void* const* d_in, const int* in_sizes, int n_in,
                              void* d_out, int out_size)
{
    const float* x     = (const float*)d_in[0];
    const int*   eidx  = (const int*)  d_in[1];
    const int*   batch = (const int*)  d_in[2];
    const int*   src   = eidx;
    const int*   dst   = eidx + EE;

    const float* W[3]   = { (const float*)d_in[3],  (const float*)d_in[7],  (const float*)d_in[11] };
    const float* b[3]   = { (const float*)d_in[4],  (const float*)d_in[8],  (const float*)d_in[12] };
    const float* gam[3] = { (const float*)d_in[5],  (const float*)d_in[9],  (const float*)d_in[13] };
    const float* bet[3] = { (const float*)d_in[6],  (const float*)d_in[10], (const float*)d_in[14] };

    float* out = (float*)d_out;

    float* d_relu;
    cudaGetSymbolAddress((void**)&d_relu, g_out);

    // lazily create side stream + events on the first (non-captured) call
    static cudaStream_t s2 = nullptr;
    static cudaEvent_t  evFork = nullptr, evJoin = nullptr;
    if (!s2) {
        cudaStreamCreateWithFlags(&s2, cudaStreamNonBlocking);
        cudaEventCreateWithFlags(&evFork, cudaEventDisableTiming);
        cudaEventCreateWithFlags(&evJoin, cudaEventDisableTiming);
    }

    // init, then fork: layer-0 GEMM (independent of graph structure) on s2
    k_init<<<(NN + 255) / 256, 256>>>(out);
    cudaEventRecord(evFork, 0);
    cudaStreamWaitEvent(s2, evFork, 0);
    k_gemm<<<(NN + 127) / 128, 128, 0, s2>>>(x, W[0]);
    cudaEventRecord(evJoin, s2);

    // CSR build on the main stream (overlaps gemm0)
    k_deg   <<<(EE + 255) / 256, 256>>>(dst);
    k_scan1 <<<NBLK, SCAN_B>>>();
    k_scan2 <<<1, 128>>>();
    k_scan3 <<<(NN + 255) / 256, 256>>>(batch);
    k_bucket<<<(EE + 255) / 256, 256>>>(src, dst);
    cudaStreamWaitEvent(0, evJoin, 0);

    for (int l = 0; l < 3; l++) {
        if (l > 0)
            k_gemm<<<(NN + 127) / 128, 128>>>(d_relu, W[l]);
        k_agg<<<NN / 16, 256>>>(b[l], batch, out + l * 64, l);
        k_bn <<<1, 64>>>(gam[l], bet[l], (l < 2) ? W[l + 1] : nullptr, l);
    }
    k_fin<<<(NN * 16 + 255) / 256, 256>>>(out, out + (size_t)GG * 192);
}

// round 14
// speedup vs baseline: 1.7525x; 1.0099x over previous
#include <cuda_runtime.h>
#include <cuda_fp16.h>
#include <cuda_bf16.h>

#define NN 100000
#define EE 1000000
#define HH 64
#define GG 512
#define BN_EPS 1e-5f

#define SCAN_B 1024
#define NBLK ((NN + SCAN_B - 1) / SCAN_B)   // 98

typedef unsigned long long ull;

// ---------------- device scratch (no allocations allowed) ----------------
__device__ __align__(16) __half g_hl16[NN * HH]; // lin output (fp16 payload, NOT dinv-scaled)
__device__ __align__(16) float  g_out[NN * HH];  // relu(agg+bias) raw layer output
__device__ float g_dinv[NN];
__device__ int   g_edeg[NN];        // edge-only in-degree
__device__ int   g_off [NN + 1];    // CSR offsets
__device__ int   g_cur [NN];        // bucket cursors
__device__ int   g_esrc[EE];        // src index bucketed by dst
__device__ int   g_part[NBLK];      // scan partials
__device__ int   g_cnt [GG];
__device__ float g_sum  [3 * HH];
__device__ float g_sumsq[3 * HH];
__device__ __align__(16) float g_scale [HH];      // rolling: BN scale of previous layer
__device__ __align__(16) float g_dconst[HH];      // rolling: BN shift of previous layer
__device__ __align__(16) float g_cvec  [HH];      // dconst @ W_next^T
__device__ __align__(16) float g_scaleA [3 * HH]; // archived per-layer BN params
__device__ __align__(16) float g_dconstA[3 * HH];

// ---------------- f32x2 helpers ----------------
__device__ __forceinline__ ull fma2(ull a, ull b, ull c) {
    ull d;
    asm("fma.rn.f32x2 %0, %1, %2, %3;" : "=l"(d) : "l"(a), "l"(b), "l"(c));
    return d;
}
__device__ __forceinline__ ull dup2(float x) {
    ull d;
    unsigned r = __float_as_uint(x);
    asm("mov.b64 %0, {%1, %1};" : "=l"(d) : "r"(r));
    return d;
}
__device__ __forceinline__ float2 unp2(ull a) {
    unsigned lo, hi;
    asm("mov.b64 {%0, %1}, %2;" : "=r"(lo), "=r"(hi) : "l"(a));
    return make_float2(__uint_as_float(lo), __uint_as_float(hi));
}
__device__ __forceinline__ float4 h4f4(uint2 u) {
    __half2 a = *reinterpret_cast<__half2*>(&u.x);
    __half2 b = *reinterpret_cast<__half2*>(&u.y);
    float2 fa = __half22float2(a), fb = __half22float2(b);
    return make_float4(fa.x, fa.y, fb.x, fb.y);
}
__device__ __forceinline__ void pdl_wait() { cudaGridDependencySynchronize(); }

// ---------------- init ----------------
__global__ void k_init(float* __restrict__ dout)
{
    int i = blockIdx.x * blockDim.x + threadIdx.x;
    if (i < NN)            g_edeg[i] = 0;
    if (i < GG * 3 * HH)   dout[i]  = 0.0f;       // pooled region
    if (i < 3 * HH) { g_sum[i] = 0.0f; g_sumsq[i] = 0.0f; }
    if (i < HH)     { g_scale[i] = 1.0f; g_dconst[i] = 0.0f; g_cvec[i] = 0.0f; }
    if (i < GG)       g_cnt[i] = 0;
}

// ---------------- edge-only in-degree over dst (4 edges/thread) ----------
__global__ void k_deg(const int* __restrict__ dst)
{
    int t = blockIdx.x * blockDim.x + threadIdx.x;
    if (t >= EE / 4) return;
    pdl_wait();
    int4 d = ((const int4*)dst)[t];
    atomicAdd(&g_edeg[d.x], 1);
    atomicAdd(&g_edeg[d.y], 1);
    atomicAdd(&g_edeg[d.z], 1);
    atomicAdd(&g_edeg[d.w], 1);
}

// ---------------- exclusive scan of g_edeg -> g_off ----------------------
__global__ __launch_bounds__(SCAN_B) void k_scan1()
{
    __shared__ int sh[SCAN_B];
    int t = threadIdx.x;
    int i = blockIdx.x * SCAN_B + t;
    pdl_wait();
    int v = (i < NN) ? g_edeg[i] : 0;
    sh[t] = v;
    __syncthreads();
    int val = v;
    for (int d = 1; d < SCAN_B; d <<= 1) {
        int add = (t >= d) ? sh[t - d] : 0;
        __syncthreads();
        val += add;
        sh[t] = val;
        __syncthreads();
    }
    if (i < NN) g_off[i] = val - v;                // local exclusive
    if (t == SCAN_B - 1) g_part[blockIdx.x] = val; // block total
}

// scan finalize (per-block redundant scan of 98 partials) + dinv + counts
__global__ __launch_bounds__(256) void k_scan3(const int* __restrict__ batch)
{
    __shared__ int ws[4];
    __shared__ int sExcl[128];
    int t = threadIdx.x;            // 256
    pdl_wait();
    if (t < 128) {
        int v = (t < NBLK) ? g_part[t] : 0;
        int lane = t & 31, w = t >> 5;
        int inc = v;
#pragma unroll
        for (int d = 1; d < 32; d <<= 1) {
            int n = __shfl_up_sync(0xFFFFFFFFu, inc, d);
            if (lane >= d) inc += n;
        }
        if (lane == 31) ws[w] = inc;
        sExcl[t] = inc - v;
    }
    __syncthreads();
    if (t < 128) {
        int w = t >> 5;
        int base = 0;
        for (int j = 0; j < w; j++) base += ws[j];
        sExcl[t] += base;
    }
    __syncthreads();

    int i = blockIdx.x * 256 + t;
    if (i < NN) {
        int o = g_off[i] + sExcl[i / SCAN_B];
        g_off[i] = o;
        g_cur[i] = o;
        g_dinv[i] = rsqrtf((float)(g_edeg[i] + 1));   // +1 self loop
    }
    if (i == 0) g_off[NN] = EE;

    int start = i * 16;
    if (start < NN) {
        int end = min(start + 16, NN);
        int curg = batch[start], acc = 0;
        for (int n = start; n < end; n++) {
            int gi = batch[n];
            if (gi != curg) { atomicAdd(&g_cnt[curg], acc); curg = gi; acc = 0; }
            acc++;
        }
        atomicAdd(&g_cnt[curg], acc);
    }
}

// ---------------- bucket edges by dst (4 edges/thread) -------------------
__global__ void k_bucket(const int* __restrict__ src, const int* __restrict__ dst)
{
    int t = blockIdx.x * blockDim.x + threadIdx.x;
    if (t >= EE / 4) return;
    pdl_wait();
    int4 s = ((const int4*)src)[t];
    int4 d = ((const int4*)dst)[t];
    int p0 = atomicAdd(&g_cur[d.x], 1);
    int p1 = atomicAdd(&g_cur[d.y], 1);
    int p2 = atomicAdd(&g_cur[d.z], 1);
    int p3 = atomicAdd(&g_cur[d.w], 1);
    g_esrc[p0] = s.x;
    g_esrc[p1] = s.y;
    g_esrc[p2] = s.z;
    g_esrc[p3] = s.w;
}

// ---------------- fused GEMM: HL = (scale*X + dconst) @ W^T  -------------
// = X @ (W*scale)^T + cvec.  Writes g_hl16 (fp16; dinv deferred into k_agg).
__global__ __launch_bounds__(128) void k_gemm(const float* __restrict__ X,
                                              const float* __restrict__ W)
{
    __shared__ __align__(16) float  sW[HH * HH];   // sW[k*64+o] = W[o][k]*scale[k]
    __shared__ float4 sX[128 * 17];
    int tid  = threadIdx.x;
    int base = blockIdx.x * 128;

    pdl_wait();   // g_scale/g_cvec from k_bn; X = g_out from k_agg

    for (int i = tid; i < HH * HH; i += 128) {
        int o = i >> 6, k = i & 63;
        sW[k * HH + o] = W[i] * g_scale[k];
    }
    for (int i = tid; i < 128 * 16; i += 128) {
        int r = i >> 4, c4 = i & 15;
        int node = base + r;
        float4 v = make_float4(0.f, 0.f, 0.f, 0.f);
        if (node < NN) v = ((const float4*)X)[(size_t)node * 16 + c4];
        sX[r * 17 + c4] = v;
    }
    __syncthreads();

    int oh = tid & 1;
    int pn = tid >> 1;
    int n0 = base + pn, n1 = base + 64 + pn;

    ull a0[16], a1[16];
    const ulonglong2* cv = (const ulonglong2*)(g_cvec + oh * 32);
#pragma unroll
    for (int j = 0; j < 8; j++) {
        ulonglong2 c = cv[j];
        a0[2*j] = c.x; a0[2*j+1] = c.y;
        a1[2*j] = c.x; a1[2*j+1] = c.y;
    }

#pragma unroll 4
    for (int k4 = 0; k4 < 16; k4++) {
        float4 xv0 = sX[pn * 17 + k4];
        float4 xv1 = sX[(pn + 64) * 17 + k4];
#pragma unroll
        for (int kk = 0; kk < 4; kk++) {
            float xs0 = (kk == 0) ? xv0.x : (kk == 1) ? xv0.y : (kk == 2) ? xv0.z : xv0.w;
            float xs1 = (kk == 0) ? xv1.x : (kk == 1) ? xv1.y : (kk == 2) ? xv1.z : xv1.w;
            ull xx0 = dup2(xs0);
            ull xx1 = dup2(xs1);
            const ulonglong2* wr = (const ulonglong2*)(sW + (k4 * 4 + kk) * HH + oh * 32);
#pragma unroll
            for (int j = 0; j < 8; j++) {
                ulonglong2 w = wr[j];
                a0[2*j]   = fma2(xx0, w.x, a0[2*j]);
                a0[2*j+1] = fma2(xx0, w.y, a0[2*j+1]);
                a1[2*j]   = fma2(xx1, w.x, a1[2*j]);
                a1[2*j+1] = fma2(xx1, w.y, a1[2*j+1]);
            }
        }
    }

    if (n0 < NN) {
        uint2* hl = (uint2*)(g_hl16 + (size_t)n0 * HH + oh * 32);
#pragma unroll
        for (int j = 0; j < 8; j++) {
            float2 lo = unp2(a0[2*j]), hi = unp2(a0[2*j+1]);
            __half2 h0 = __float22half2_rn(lo);
            __half2 h1 = __float22half2_rn(hi);
            hl[j] = make_uint2(*(unsigned*)&h0, *(unsigned*)&h1);
        }
    }
    if (n1 < NN) {
        uint2* hl = (uint2*)(g_hl16 + (size_t)n1 * HH + oh * 32);
#pragma unroll
        for (int j = 0; j < 8; j++) {
            float2 lo = unp2(a1[2*j]), hi = unp2(a1[2*j+1]);
            __half2 h0 = __float22half2_rn(lo);
            __half2 h1 = __float22half2_rn(hi);
            hl[j] = make_uint2(*(unsigned*)&h0, *(unsigned*)&h1);
        }
    }
}

// ---- fused pull-aggregate + bias + relu + BN stats + raw segment pool ----
__global__ __launch_bounds__(256) void k_agg(const float* __restrict__ b,
                                             const int* __restrict__ batch,
                                             float* __restrict__ pool, int layer)
{
    int tid = threadIdx.x;
    int grp = tid >> 4;
    int q   = tid & 15;
    int node = blockIdx.x * 16 + grp;      // grid is exactly NN/16

    unsigned mask = 0xFFFFu << (((tid & 31) >> 4) << 4);

    pdl_wait();   // g_hl16 from k_gemm; CSR from setup

    const uint2* hl2 = (const uint2*)g_hl16;   // 8B = 4 halves per element
    float di = g_dinv[node];
    float4 vs = h4f4(hl2[(size_t)node * 16 + q]);
    float4 acc = make_float4(vs.x * di, vs.y * di, vs.z * di, vs.w * di);

    int beg = g_off[node], end = g_off[node + 1];
    for (int p = beg; p < end; p += 16) {
        int rem = end - p;                                  // group-uniform
        int idx = (q < rem) ? g_esrc[p + q] : 0;
        float dsl = g_dinv[idx];

        uint2 v[8];
        float w[8];
#pragma unroll
        for (int j = 0; j < 8; j++) {
            int s = __shfl_sync(mask, idx, j, 16);
            w[j]  = __shfl_sync(mask, dsl, j, 16);
            v[j]  = hl2[(size_t)s * 16 + q];
        }
#pragma unroll
        for (int j = 0; j < 8; j++) {
            if (j < rem) {
                float4 f = h4f4(v[j]);
                acc.x = fmaf(f.x, w[j], acc.x);
                acc.y = fmaf(f.y, w[j], acc.y);
                acc.z = fmaf(f.z, w[j], acc.z);
                acc.w = fmaf(f.w, w[j], acc.w);
            }
        }
        if (rem > 8) {
#pragma unroll
            for (int j = 0; j < 8; j++) {
                int s = __shfl_sync(mask, idx, 8 + j, 16);
                w[j]  = __shfl_sync(mask, dsl, 8 + j, 16);
                v[j]  = hl2[(size_t)s * 16 + q];
            }
#pragma unroll
            for (int j = 0; j < 8; j++) {
                if (8 + j < rem) {
                    float4 f = h4f4(v[j]);
                    acc.x = fmaf(f.x, w[j], acc.x);
                    acc.y = fmaf(f.y, w[j], acc.y);
                    acc.z = fmaf(f.z, w[j], acc.z);
                    acc.w = fmaf(f.w, w[j], acc.w);
                }
            }
        }
    }

    float4 bv = ((const float4*)b)[q];
    float4 y;
    y.x = fmaxf(fmaf(acc.x, di, bv.x), 0.f);
    y.y = fmaxf(fmaf(acc.y, di, bv.y), 0.f);
    y.z = fmaxf(fmaf(acc.z, di, bv.z), 0.f);
    y.w = fmaxf(fmaf(acc.w, di, bv.w), 0.f);
    ((float4*)g_out)[(size_t)node * 16 + q] = y;

    __shared__ float sY[16][HH + 4];
    __shared__ int   sB[16];
    sY[grp][q*4+0] = y.x;
    sY[grp][q*4+1] = y.y;
    sY[grp][q*4+2] = y.z;
    sY[grp][q*4+3] = y.w;
    if (q == 0) sB[grp] = batch[node];
    __syncthreads();

    if (tid < HH) {
        int c = tid;
        float s = 0.f, s2 = 0.f, pacc = 0.f;
        int curg = sB[0];
#pragma unroll
        for (int g2 = 0; g2 < 16; g2++) {
            float v = sY[g2][c];
            s += v;
            s2 = fmaf(v, v, s2);
            int gi = sB[g2];
            if (gi != curg) {
                atomicAdd(&pool[(size_t)curg * 192 + c], pacc);
                curg = gi; pacc = 0.f;
            }
            pacc += v;
        }
        atomicAdd(&pool[(size_t)curg * 192 + c], pacc);
        atomicAdd(&g_sum  [layer * HH + c], s);
        atomicAdd(&g_sumsq[layer * HH + c], s2);
    }
}

// ---------------- BN params + fused constant vector for next GEMM --------
__global__ void k_bn(const float* __restrict__ g, const float* __restrict__ beta,
                     const float* __restrict__ Wnext, int layer)
{
    int c = threadIdx.x;   // 64
    pdl_wait();
    float m   = g_sum  [layer * HH + c] * (1.0f / NN);
    float var = g_sumsq[layer * HH + c] * (1.0f / NN) - m * m;
    float r  = rsqrtf(var + BN_EPS);
    float sc = g[c] * r;
    float dc = beta[c] - m * sc;
    g_scale[c]  = sc;
    g_dconst[c] = dc;
    g_scaleA [layer * HH + c] = sc;
    g_dconstA[layer * HH + c] = dc;

    __shared__ float sdc[HH];
    sdc[c] = dc;
    __syncthreads();
    if (Wnext) {
        float acc = 0.f;
#pragma unroll 8
        for (int k = 0; k < HH; k++) acc = fmaf(sdc[k], Wnext[c * HH + k], acc);
        g_cvec[c] = acc;
    }
}

// ---- finale: all 3 pool fixups + BN-applied final h output --------------
__global__ void k_fin(float* __restrict__ out, float* __restrict__ outh)
{
    int idx = blockIdx.x * blockDim.x + threadIdx.x;
    pdl_wait();

    if (idx < GG * HH) {
        int gph = idx >> 6, c = idx & 63;
        float cntf = (float)g_cnt[gph];
#pragma unroll
        for (int l = 0; l < 3; l++) {
            float* p = out + (size_t)gph * 192 + l * 64 + c;
            float raw = *p;
            *p = g_scaleA[l * HH + c] * raw + cntf * g_dconstA[l * HH + c];
        }
    }

    if (idx < NN * 16) {
        float4 v = ((const float4*)g_out)[idx];
        int c = (idx & 15) * 4;
        v.x = v.x * g_scaleA[2*HH + c]     + g_dconstA[2*HH + c];
        v.y = v.y * g_scaleA[2*HH + c + 1] + g_dconstA[2*HH + c + 1];
        v.z = v.z * g_scaleA[2*HH + c + 2] + g_dconstA[2*HH + c + 2];
        v.w = v.w * g_scaleA[2*HH + c + 3] + g_dconstA[2*HH + c + 3];
        ((float4*)outh)[idx] = v;
    }
}

// ---------------- PDL launch helper ----------------
template <typename F, typename... Args>
static inline void launch_pdl(F* f, dim3 grid, dim3 block, cudaStream_t st, Args... args)
{
    cudaLaunchConfig_t cfg = {};
    cfg.gridDim = grid;
    cfg.blockDim = block;
    cfg.dynamicSmemBytes = 0;
    cfg.stream = st;
    cudaLaunchAttribute at[1];
    at[0].id = cudaLaunchAttributeProgrammaticStreamSerialization;
    at[0].val.programmaticStreamSerializationAllowed = 1;
    cfg.attrs = at;
    cfg.numAttrs = 1;
    cudaLaunchKernelEx(&cfg, f, args...);
}

// ---------------- host launcher ----------------
extern "C" void kernel_launch(void* const* d_in, const int* in_sizes, int n_in,
                              void* d_out, int out_size)
{
    const float* x     = (const float*)d_in[0];
    const int*   eidx  = (const int*)  d_in[1];
    const int*   batch = (const int*)  d_in[2];
    const int*   src   = eidx;
    const int*   dst   = eidx + EE;

    const float* W[3]   = { (const float*)d_in[3],  (const float*)d_in[7],  (const float*)d_in[11] };
    const float* b[3]   = { (const float*)d_in[4],  (const float*)d_in[8],  (const float*)d_in[12] };
    const float* gam[3] = { (const float*)d_in[5],  (const float*)d_in[9],  (const float*)d_in[13] };
    const float* bet[3] = { (const float*)d_in[6],  (const float*)d_in[10], (const float*)d_in[14] };

    float* out = (float*)d_out;

    float* d_relu;
    cudaGetSymbolAddress((void**)&d_relu, g_out);

    // lazily create side stream + events on the first (non-captured) call
    static cudaStream_t s2 = nullptr;
    static cudaEvent_t  evFork = nullptr, evJoin = nullptr;
    if (!s2) {
        cudaStreamCreateWithFlags(&s2, cudaStreamNonBlocking);
        cudaEventCreateWithFlags(&evFork, cudaEventDisableTiming);
        cudaEventCreateWithFlags(&evJoin, cudaEventDisableTiming);
    }

    // init, then fork: layer-0 GEMM (independent of graph structure) on s2
    k_init<<<(NN + 255) / 256, 256>>>(out);
    cudaEventRecord(evFork, 0);
    cudaStreamWaitEvent(s2, evFork, 0);
    k_gemm<<<(NN + 127) / 128, 128, 0, s2>>>(x, W[0]);
    cudaEventRecord(evJoin, s2);

    // CSR build on the main stream (overlaps gemm0), PDL-chained
    launch_pdl(k_deg,   dim3((EE / 4 + 255) / 256), dim3(256), (cudaStream_t)0, dst);
    launch_pdl(k_scan1, dim3(NBLK), dim3(SCAN_B), (cudaStream_t)0);
    launch_pdl(k_scan3, dim3((NN + 255) / 256), dim3(256), (cudaStream_t)0, batch);
    launch_pdl(k_bucket,dim3((EE / 4 + 255) / 256), dim3(256), (cudaStream_t)0, src, dst);
    cudaStreamWaitEvent(0, evJoin, 0);

    for (int l = 0; l < 3; l++) {
        if (l > 0)
            launch_pdl(k_gemm, dim3((NN + 127) / 128), dim3(128), (cudaStream_t)0,
                       (const float*)d_relu, W[l]);
        launch_pdl(k_agg, dim3(NN / 16), dim3(256), (cudaStream_t)0,
                   b[l], batch, out + l * 64, l);
        launch_pdl(k_bn, dim3(1), dim3(64), (cudaStream_t)0,
                   gam[l], bet[l], (l < 2) ? W[l + 1] : (const float*)nullptr, l);
    }
    launch_pdl(k_fin, dim3((NN * 16 + 255) / 256), dim3(256), (cudaStream_t)0,
               out, out + (size_t)GG * 192);
}